// round 7
// baseline (speedup 1.0000x reference)
#include <cuda_runtime.h>
#include <cuda_fp16.h>
#include <cstdint>

#define HID 256
#define LC 512
#define NCH 256
#define PLANE (HID*LC)

// Activation ping-pong buffers: packed (hi,lo) half2 per element, or fp32 at the ends.
__device__ float g_bufA[(size_t)NCH * PLANE];
__device__ float g_bufB[(size_t)NCH * PLANE];

// Fragment-layout weights: [layer][kt][mtile][lane] -> uint4 (8 halves, mma A-frag order)
__device__ uint4 WC_hi[7 * 48 * 16 * 32];
__device__ uint4 WC_lo[7 * 48 * 16 * 32];
__device__ uint4 WP_hi[18 * 16 * 32];
__device__ uint4 WP_lo[18 * 16 * 32];

// ---------------------------------------------------------------------------
__device__ __forceinline__ uint32_t smem_u32(const void* p) {
    uint32_t a;
    asm("{ .reg .u64 t; cvta.to.shared.u64 t, %1; cvt.u32.u64 %0, t; }" : "=r"(a) : "l"(p));
    return a;
}
__device__ __forceinline__ float gelu_res(float c) {
    return fmaf(0.5f * c, 1.0f + erff(c * 0.70710678118654752440f), c);
}
__device__ __forceinline__ uint32_t pack_hl(float v) {
    __half hh = __float2half_rn(v);
    float res = v - __half2float(hh);
    return (uint32_t)__half_as_ushort(hh) |
           ((uint32_t)__half_as_ushort(__float2half_rn(res)) << 16);
}
__device__ __forceinline__ void mma16816(float* d, const uint4 a, uint32_t b0, uint32_t b1) {
    asm volatile(
        "mma.sync.aligned.m16n8k16.row.col.f32.f16.f16.f32 "
        "{%0,%1,%2,%3}, {%4,%5,%6,%7}, {%8,%9}, {%0,%1,%2,%3};"
        : "+f"(d[0]), "+f"(d[1]), "+f"(d[2]), "+f"(d[3])
        : "r"(a.x), "r"(a.y), "r"(a.z), "r"(a.w), "r"(b0), "r"(b1));
}
__device__ __forceinline__ void ldmx4(uint32_t& r0, uint32_t& r1, uint32_t& r2, uint32_t& r3,
                                      uint32_t addr) {
    asm volatile("ldmatrix.sync.aligned.m8n8.x4.shared.b16 {%0,%1,%2,%3}, [%4];"
                 : "=r"(r0), "=r"(r1), "=r"(r2), "=r"(r3) : "r"(addr));
}
__device__ __forceinline__ void ldmx4t(uint32_t& r0, uint32_t& r1, uint32_t& r2, uint32_t& r3,
                                       uint32_t addr) {
    asm volatile("ldmatrix.sync.aligned.m8n8.x4.trans.shared.b16 {%0,%1,%2,%3}, [%4];"
                 : "=r"(r0), "=r"(r1), "=r"(r2), "=r"(r3) : "r"(addr));
}
__device__ __forceinline__ uint4 lds128(uint32_t addr) {
    uint4 r;
    asm volatile("ld.shared.v4.u32 {%0,%1,%2,%3}, [%4];"
                 : "=r"(r.x), "=r"(r.y), "=r"(r.z), "=r"(r.w) : "r"(addr));
    return r;
}
__device__ __forceinline__ void cp16(uint32_t dst, const void* src) {
    asm volatile("cp.async.cg.shared.global [%0], [%1], 16;" :: "r"(dst), "l"(src));
}
#define CP_COMMIT() asm volatile("cp.async.commit_group;" ::: "memory")
#define CP_WAIT0()  asm volatile("cp.async.wait_group 0;" ::: "memory")

// ---------------------------------------------------------------------------
// Weight prep: fp32 -> (hi,lo) fp16 in mma A-fragment order.
// ---------------------------------------------------------------------------
__device__ __forceinline__ void split_pack(const float* v, uint4& hi, uint4& lo) {
    uint32_t hx[4], lx[4];
#pragma unroll
    for (int q = 0; q < 4; q++) {
        float a = v[2 * q], b = v[2 * q + 1];
        __half ah = __float2half_rn(a), bh = __float2half_rn(b);
        float ar = a - __half2float(ah), br = b - __half2float(bh);
        hx[q] = (uint32_t)__half_as_ushort(ah) | ((uint32_t)__half_as_ushort(bh) << 16);
        lx[q] = (uint32_t)__half_as_ushort(__float2half_rn(ar)) |
                ((uint32_t)__half_as_ushort(__float2half_rn(br)) << 16);
    }
    hi = make_uint4(hx[0], hx[1], hx[2], hx[3]);
    lo = make_uint4(lx[0], lx[1], lx[2], lx[3]);
}

__global__ void prep_conv_w(const float* __restrict__ tw) {
    int idx = blockIdx.x * 256 + threadIdx.x;
    if (idx >= 7 * 48 * 16 * 32) return;
    int lane = idx & 31;
    int mt = (idx >> 5) & 15;
    int kt = (idx >> 9) % 48;
    int layer = (idx >> 9) / 48;
    int g = lane >> 2, t = lane & 3;
    const float* W = tw + (size_t)layer * 256 * 768;
    int r0 = mt * 16 + g, r1 = r0 + 8;
    int c0 = kt * 16 + 2 * t;
    float v[8];
    v[0] = W[r0 * 768 + c0];     v[1] = W[r0 * 768 + c0 + 1];
    v[2] = W[r1 * 768 + c0];     v[3] = W[r1 * 768 + c0 + 1];
    v[4] = W[r0 * 768 + c0 + 8]; v[5] = W[r0 * 768 + c0 + 9];
    v[6] = W[r1 * 768 + c0 + 8]; v[7] = W[r1 * 768 + c0 + 9];
    split_pack(v, WC_hi[idx], WC_lo[idx]);
}

__global__ void prep_proj_w(const float* __restrict__ wp) {
    int idx = blockIdx.x * 256 + threadIdx.x;
    if (idx >= 18 * 16 * 32) return;
    int lane = idx & 31;
    int mt = (idx >> 5) & 15;
    int kt = idx >> 9;
    int g = lane >> 2, t = lane & 3;
    int r0 = mt * 16 + g, r1 = r0 + 8;
    int c0 = kt * 16 + 2 * t;
    const int cs[4] = {c0, c0 + 1, c0 + 8, c0 + 9};
    float v[8];
    v[0] = (cs[0] < 283) ? wp[r0 * 283 + cs[0]] : 0.f;
    v[1] = (cs[1] < 283) ? wp[r0 * 283 + cs[1]] : 0.f;
    v[2] = (cs[0] < 283) ? wp[r1 * 283 + cs[0]] : 0.f;
    v[3] = (cs[1] < 283) ? wp[r1 * 283 + cs[1]] : 0.f;
    v[4] = (cs[2] < 283) ? wp[r0 * 283 + cs[2]] : 0.f;
    v[5] = (cs[3] < 283) ? wp[r0 * 283 + cs[3]] : 0.f;
    v[6] = (cs[2] < 283) ? wp[r1 * 283 + cs[2]] : 0.f;
    v[7] = (cs[3] < 283) ? wp[r1 * 283 + cs[3]] : 0.f;
    split_pack(v, WP_hi[idx], WP_lo[idx]);
}

// ---------------------------------------------------------------------------
// Projection kernel (validated): C[256co][131072r] = Wp * X^T.
// Writes packed (hi,lo) activations to g_bufA.
// ---------------------------------------------------------------------------
__global__ __launch_bounds__(256, 1) void proj_kernel(const float* __restrict__ xin) {
    constexpr int KT = 18;
    __shared__ unsigned short Bs[2][2][128 * 24];

    const int tid = threadIdx.x;
    const int lane = tid & 31;
    const int wid = tid >> 5;
    const int wm = wid >> 2;
    const int wn = wid & 3;
    const int mbase = blockIdx.y * 128;
    const int rbase = blockIdx.x * 128;

    const int kk = tid & 15;
    const int lrow = tid >> 4;
    uint32_t vr[8];

    auto gather = [&](int kt) {
        int m = kt * 16 + kk;
#pragma unroll
        for (int e = 0; e < 8; e++) {
            float v = 0.f;
            if (m < 283) v = xin[(size_t)(rbase + lrow + e * 16) * 283 + m];
            vr[e] = pack_hl(v);
        }
    };
    auto stsB = [&](int s) {
#pragma unroll
        for (int e = 0; e < 8; e++) {
            int l = lrow + e * 16;
            Bs[s][0][l * 24 + kk] = (unsigned short)(vr[e] & 0xffff);
            Bs[s][1][l * 24 + kk] = (unsigned short)(vr[e] >> 16);
        }
    };

    uint4 Ah[2][4], Al[2][4];
    auto loadA = [&](int kt, int b) {
#pragma unroll
        for (int i = 0; i < 4; i++) {
            int mt = blockIdx.y * 8 + wm * 4 + i;
            size_t o = (size_t)(kt * 16 + mt) * 32 + lane;
            Ah[b][i] = WP_hi[o];
            Al[b][i] = WP_lo[o];
        }
    };

    float acc[4][4][4];
#pragma unroll
    for (int i = 0; i < 4; i++)
#pragma unroll
        for (int j = 0; j < 4; j++)
#pragma unroll
            for (int q = 0; q < 4; q++) acc[i][j][q] = 0.f;

    gather(0); stsB(0); loadA(0, 0);
    __syncthreads();

    const uint32_t sbase = smem_u32(Bs);
    const int rsel = (lane & 7) + ((lane & 16) ? 8 : 0);
    const int csel = (lane & 8) ? 8 : 0;

    auto body = [&](int kt, int s) {
        if (kt + 1 < KT) { gather(kt + 1); loadA(kt + 1, s ^ 1); }
        uint32_t bh[4][2], bl[4][2];
#pragma unroll
        for (int pr = 0; pr < 2; pr++) {
            int row = wn * 32 + pr * 16 + rsel;
            uint32_t ah = sbase + (uint32_t)(((s * 2 + 0) * 3072 + row * 24 + csel) * 2);
            uint32_t al = sbase + (uint32_t)(((s * 2 + 1) * 3072 + row * 24 + csel) * 2);
            uint32_t r0, r1, r2, r3;
            ldmx4(r0, r1, r2, r3, ah);
            bh[pr * 2][0] = r0; bh[pr * 2][1] = r1;
            bh[pr * 2 + 1][0] = r2; bh[pr * 2 + 1][1] = r3;
            ldmx4(r0, r1, r2, r3, al);
            bl[pr * 2][0] = r0; bl[pr * 2][1] = r1;
            bl[pr * 2 + 1][0] = r2; bl[pr * 2 + 1][1] = r3;
        }
#pragma unroll
        for (int i = 0; i < 4; i++)
#pragma unroll
            for (int j = 0; j < 4; j++) {
                mma16816(acc[i][j], Ah[s][i], bh[j][0], bh[j][1]);
                mma16816(acc[i][j], Ah[s][i], bl[j][0], bl[j][1]);
                mma16816(acc[i][j], Al[s][i], bh[j][0], bh[j][1]);
            }
        if (kt + 1 < KT) stsB(s ^ 1);
        __syncthreads();
    };

    for (int kt2 = 0; kt2 < KT; kt2 += 2) { body(kt2, 0); body(kt2 + 1, 1); }

    const int g = lane >> 2, t4 = lane & 3;
    int nn = rbase >> 9;
    int lp0 = rbase & 511;
    uint32_t* outp = (uint32_t*)g_bufA + (size_t)nn * PLANE;
#pragma unroll
    for (int i = 0; i < 4; i++) {
        int co0 = mbase + wm * 64 + i * 16 + g;
#pragma unroll
        for (int j = 0; j < 4; j++) {
            int lp = lp0 + wn * 32 + j * 8 + 2 * t4;
            uint2 v0, v1;
            v0.x = pack_hl(acc[i][j][0]); v0.y = pack_hl(acc[i][j][1]);
            v1.x = pack_hl(acc[i][j][2]); v1.y = pack_hl(acc[i][j][3]);
            *(uint2*)&outp[(size_t)co0 * 512 + lp] = v0;
            *(uint2*)&outp[(size_t)(co0 + 8) * 512 + lp] = v1;
        }
    }
}

// ---------------------------------------------------------------------------
// Conv layer kernel v3: warp tile 64x64, CTA tile 128(M) x 256(N), 8 warps.
// cp.async A pipeline + 4-slot B ring (1 barrier / 2 kt). 1 CTA/SM.
// MODE 1: packed half2 out; MODE 2: fp32 out (last layer). gelu+res epilogue.
// ---------------------------------------------------------------------------
#define SSTR2 264                 // halves per k-row (256 + 8 pad)
#define A_REG 32768               // 4 slots x 8KB (hi 4KB + lo 4KB)
#define B_PLANE2 8448             // 16 k x 264 halves x 2B
#define SMEM_CONV (A_REG + 8 * B_PLANE2)

__device__ __forceinline__ uint2 ld2_guard(const uint32_t* row, int base) {
    if ((unsigned)base <= 510u) return *(const uint2*)(row + base);
    uint2 r;
    r.x = ((unsigned)(base)     < 512u) ? row[base]     : 0u;
    r.y = ((unsigned)(base + 1) < 512u) ? row[base + 1] : 0u;
    return r;
}

template <int MODE, bool A2B>
__global__ __launch_bounds__(256, 1) void conv_kernel(
    const float* __restrict__ bias, int dil, int layer)
{
    extern __shared__ char dsm[];
    const uint32_t sm0 = smem_u32(dsm);
    const uint32_t sA = sm0;
    const uint32_t sB = sm0 + A_REG;
    char* bptr = dsm + A_REG;

    const int tid = threadIdx.x;
    const int lane = tid & 31;
    const int wid = tid >> 5;
    const int wm = wid >> 2;      // 0..1  (64 M rows each)
    const int wn = wid & 3;       // 0..3  (64 N cols each)
    const int mbase = blockIdx.y * 128;
    const int mt8 = blockIdx.y * 8;
    const int n = blockIdx.z;
    const int l0 = blockIdx.x * 256;

    const uint4* __restrict__ WAhi = WC_hi + (size_t)layer * 48 * 16 * 32;
    const uint4* __restrict__ WAlo = WC_lo + (size_t)layer * 48 * 16 * 32;
    const uint32_t* __restrict__ inw =
        (const uint32_t*)(A2B ? g_bufA : g_bufB) + (size_t)n * PLANE;

    // A cp.async: 256 threads x (hi 16B + lo 16B) per kt
    const int amt = tid >> 5;                  // 0..7 local mtile
    auto cpA = [&](int kt, int q) {
        size_t src = (size_t)(kt * 16 + mt8 + amt) * 32 + lane;
        uint32_t d = sA + q * 8192 + tid * 16;
        cp16(d, WAhi + src);
        cp16(d + 4096, WAlo + src);
    };

    // B gather: thread -> (k-row kk, two 8-l units at ll0 and ll0+128)
    const int kk = tid >> 4;
    const int ll0 = (tid & 15) * 8;
    uint2 v[8];
    auto gather = [&](int kt) {
        int kg = kt * 16 + kk;
        int ci = kg / 3;
        int sh = (kg - 3 * ci - 1) * dil;
        const uint32_t* rowp = inw + ci * 512;
        int base = l0 + ll0 + sh;
        v[0] = ld2_guard(rowp, base);
        v[1] = ld2_guard(rowp, base + 2);
        v[2] = ld2_guard(rowp, base + 4);
        v[3] = ld2_guard(rowp, base + 6);
        v[4] = ld2_guard(rowp, base + 128);
        v[5] = ld2_guard(rowp, base + 130);
        v[6] = ld2_guard(rowp, base + 132);
        v[7] = ld2_guard(rowp, base + 134);
    };
    auto stsB = [&](int q) {
        char* ph = bptr + (q * 2 + 0) * B_PLANE2;
        char* pl = bptr + (q * 2 + 1) * B_PLANE2;
#pragma unroll
        for (int u = 0; u < 2; u++) {
            uint4 hv, lv;
            hv.x = (v[u*4+0].x & 0xffffu) | (v[u*4+0].y << 16);
            hv.y = (v[u*4+1].x & 0xffffu) | (v[u*4+1].y << 16);
            hv.z = (v[u*4+2].x & 0xffffu) | (v[u*4+2].y << 16);
            hv.w = (v[u*4+3].x & 0xffffu) | (v[u*4+3].y << 16);
            lv.x = (v[u*4+0].x >> 16) | (v[u*4+0].y & 0xffff0000u);
            lv.y = (v[u*4+1].x >> 16) | (v[u*4+1].y & 0xffff0000u);
            lv.z = (v[u*4+2].x >> 16) | (v[u*4+2].y & 0xffff0000u);
            lv.w = (v[u*4+3].x >> 16) | (v[u*4+3].y & 0xffff0000u);
            *(uint4*)(ph + (kk * SSTR2 + ll0 + u * 128) * 2) = hv;
            *(uint4*)(pl + (kk * SSTR2 + ll0 + u * 128) * 2) = lv;
        }
    };

    float acc[4][8][4];
#pragma unroll
    for (int i = 0; i < 4; i++)
#pragma unroll
        for (int j = 0; j < 8; j++)
#pragma unroll
            for (int q = 0; q < 4; q++) acc[i][j][q] = 0.f;

    // ldmatrix.trans lane addressing
    const int grp = lane >> 3, lwi = lane & 7;
    const int krow = (grp & 1) * 8 + lwi;
    const int ncol = wn * 64 + (grp >> 1) * 8;

    auto mma_block = [&](int q) {
        uint32_t ph = sB + (uint32_t)(q * 2 + 0) * B_PLANE2;
        uint32_t pl = sB + (uint32_t)(q * 2 + 1) * B_PLANE2;
        uint32_t bh[8][2], bl[8][2];
#pragma unroll
        for (int jj = 0; jj < 4; jj++) {
            uint32_t r0, r1, r2, r3;
            ldmx4t(r0, r1, r2, r3, ph + (uint32_t)((krow * SSTR2 + ncol + jj * 16) * 2));
            bh[jj * 2][0] = r0;     bh[jj * 2][1] = r1;
            bh[jj * 2 + 1][0] = r2; bh[jj * 2 + 1][1] = r3;
            ldmx4t(r0, r1, r2, r3, pl + (uint32_t)((krow * SSTR2 + ncol + jj * 16) * 2));
            bl[jj * 2][0] = r0;     bl[jj * 2][1] = r1;
            bl[jj * 2 + 1][0] = r2; bl[jj * 2 + 1][1] = r3;
        }
        uint32_t abase = sA + (uint32_t)q * 8192;
#pragma unroll
        for (int ih = 0; ih < 4; ih++) {
            uint32_t ao = abase + (uint32_t)(((wm * 4 + ih) * 32 + lane) * 16);
            uint4 Ah = lds128(ao);
            uint4 Al = lds128(ao + 4096);
#pragma unroll
            for (int j = 0; j < 8; j++) {
                mma16816(acc[ih][j], Ah, bh[j][0], bh[j][1]);
                mma16816(acc[ih][j], Ah, bl[j][0], bl[j][1]);
                mma16816(acc[ih][j], Al, bh[j][0], bh[j][1]);
            }
        }
    };

    // prologue: fill slots 0,1
    cpA(0, 0); cpA(1, 1); CP_COMMIT();
    gather(0); stsB(0);
    gather(1); stsB(1);
    CP_WAIT0();
    __syncthreads();

    int qc = 0;
    for (int kt2 = 0; kt2 < 48; kt2 += 2) {
        const int qn = qc ^ 2;
        const bool more = (kt2 + 2) < 48;
        if (more) { cpA(kt2 + 2, qn); cpA(kt2 + 3, qn + 1); CP_COMMIT(); }
        if (more) gather(kt2 + 2);
        mma_block(qc);
        if (more) stsB(qn);
        if (more) gather(kt2 + 3);
        mma_block(qc + 1);
        if (more) stsB(qn + 1);
        CP_WAIT0();
        __syncthreads();
        qc = qn;
    }

    // ---- epilogue ----
    const int g = lane >> 2, t4 = lane & 3;
    if (MODE == 1) {
        uint32_t* outp = (uint32_t*)(A2B ? g_bufB : g_bufA) + (size_t)n * PLANE;
#pragma unroll
        for (int i = 0; i < 4; i++) {
            int co0 = mbase + wm * 64 + i * 16 + g;
            float b0 = bias[co0], b1 = bias[co0 + 8];
#pragma unroll
            for (int j = 0; j < 8; j++) {
                int lp = l0 + wn * 64 + j * 8 + 2 * t4;
                uint2 v0, v1;
                v0.x = pack_hl(gelu_res(acc[i][j][0] + b0));
                v0.y = pack_hl(gelu_res(acc[i][j][1] + b0));
                v1.x = pack_hl(gelu_res(acc[i][j][2] + b1));
                v1.y = pack_hl(gelu_res(acc[i][j][3] + b1));
                *(uint2*)&outp[(size_t)co0 * 512 + lp] = v0;
                *(uint2*)&outp[(size_t)(co0 + 8) * 512 + lp] = v1;
            }
        }
    } else {
        float* outp = (A2B ? g_bufB : g_bufA) + (size_t)n * PLANE;
#pragma unroll
        for (int i = 0; i < 4; i++) {
            int co0 = mbase + wm * 64 + i * 16 + g;
            float b0 = bias[co0], b1 = bias[co0 + 8];
#pragma unroll
            for (int j = 0; j < 8; j++) {
                int lp = l0 + wn * 64 + j * 8 + 2 * t4;
                float2 v0, v1;
                v0.x = gelu_res(acc[i][j][0] + b0);
                v0.y = gelu_res(acc[i][j][1] + b0);
                v1.x = gelu_res(acc[i][j][2] + b1);
                v1.y = gelu_res(acc[i][j][3] + b1);
                *(float2*)&outp[(size_t)co0 * 512 + lp] = v0;
                *(float2*)&outp[(size_t)(co0 + 8) * 512 + lp] = v1;
            }
        }
    }
}

// ---------------------------------------------------------------------------
// Head: profile conv (K=20, pad (9,10)) + mean pool + atpm, fused.
// ---------------------------------------------------------------------------
__global__ __launch_bounds__(512) void head_kernel(const float* __restrict__ wprof,
                                                   const float* __restrict__ bprof,
                                                   const float* __restrict__ watpm,
                                                   const float* __restrict__ batpm,
                                                   const int* __restrict__ np_raw,
                                                   float* __restrict__ out) {
    __shared__ float buf[2][544];
    __shared__ float wp[HID * 20];
    __shared__ float wa[HID];
    __shared__ float red[16];

    const int n = blockIdx.x;
    const int tid = threadIdx.x;
    const float* h = g_bufB + (size_t)n * PLANE;

    for (int i = tid; i < HID * 20; i += 512) wp[i] = wprof[i];
    if (tid < HID) wa[tid] = watpm[tid];
    if (tid < 9)  { buf[0][tid] = 0.f; buf[1][tid] = 0.f; }
    if (tid < 13) { buf[0][521 + tid] = 0.f; buf[1][521 + tid] = 0.f; }

    float accp = 0.f, acca = 0.f;
    buf[0][9 + tid] = h[tid];
    __syncthreads();

    for (int c = 0; c < HID; c++) {
        const int cur = c & 1;
        if (c + 1 < HID) buf[cur ^ 1][9 + tid] = h[(c + 1) * LC + tid];
        acca = fmaf(buf[cur][9 + tid], wa[c], acca);
        const float* wr = &wp[c * 20];
#pragma unroll
        for (int k = 0; k < 20; k++)
            accp = fmaf(buf[cur][tid + k], wr[k], accp);
        __syncthreads();
    }

    out[256 + n * LC + tid] = accp + bprof[0];

#pragma unroll
    for (int o = 16; o > 0; o >>= 1) acca += __shfl_xor_sync(0xffffffffu, acca, o);
    if ((tid & 31) == 0) red[tid >> 5] = acca;
    __syncthreads();
    if (tid < 16) {
        float vv = red[tid];
#pragma unroll
        for (int o = 8; o > 0; o >>= 1) vv += __shfl_xor_sync(0x0000ffffu, vv, o);
        if (tid == 0) {
            int n0 = np_raw[0];
            int n1;
            int w1 = np_raw[1];
            if (w1 != 0) {
                n1 = w1;
            } else {
                int w2 = np_raw[2], w3 = np_raw[3];
                n1 = (w2 >= 0 && w2 < 128 && w3 == 0) ? w2 : 0;
            }
            float atpm = vv * (1.0f / 512.0f) + batpm[0];
            int p = n & 127, b = n >> 7;
            int lim = (b == 0) ? n0 : n1;
            out[n] = (p < lim) ? atpm : 0.f;
        }
    }
}

// ---------------------------------------------------------------------------
extern "C" void kernel_launch(void* const* d_in, const int* in_sizes, int n_in,
                              void* d_out, int out_size) {
    const float* x       = (const float*)d_in[0];
    const float* w_proj  = (const float*)d_in[1];
    const float* tower_w = (const float*)d_in[2];
    const float* tower_b = (const float*)d_in[3];
    const float* w_prof  = (const float*)d_in[4];
    const float* b_prof  = (const float*)d_in[5];
    const float* w_atpm  = (const float*)d_in[6];
    const float* b_atpm  = (const float*)d_in[7];
    const int*   n_peaks = (const int*)d_in[8];
    float* out = (float*)d_out;

    (void)in_sizes; (void)n_in; (void)out_size;

    cudaFuncSetAttribute(conv_kernel<1, true>,
                         cudaFuncAttributeMaxDynamicSharedMemorySize, SMEM_CONV);
    cudaFuncSetAttribute(conv_kernel<1, false>,
                         cudaFuncAttributeMaxDynamicSharedMemorySize, SMEM_CONV);
    cudaFuncSetAttribute(conv_kernel<2, true>,
                         cudaFuncAttributeMaxDynamicSharedMemorySize, SMEM_CONV);

    // 0) weight prep (fragment layout + fp16 hi/lo split)
    prep_conv_w<<<672, 256>>>(tower_w);
    prep_proj_w<<<36, 256>>>(w_proj);

    // 1) projection -> g_bufA (packed half2 hi/lo)
    proj_kernel<<<dim3(1024, 2, 1), 256>>>(x);

    // 2) conv tower, ping-pong; layer 6 writes fp32 into g_bufB
    dim3 gc(2, 2, NCH);   // l-tiles(256) x M-tiles(128) x chunks
    for (int i = 0; i < 7; i++) {
        int dil = 2 << i;
        const float* bl = tower_b + (size_t)i * HID;
        if (i == 6)            conv_kernel<2, true ><<<gc, 256, SMEM_CONV>>>(bl, dil, i);
        else if ((i & 1) == 0) conv_kernel<1, true ><<<gc, 256, SMEM_CONV>>>(bl, dil, i);
        else                   conv_kernel<1, false><<<gc, 256, SMEM_CONV>>>(bl, dil, i);
    }

    // 3) fused heads from g_bufB
    head_kernel<<<NCH, 512>>>(w_prof, b_prof, w_atpm, b_atpm, n_peaks, out);
}

// round 8
// speedup vs baseline: 1.1258x; 1.1258x over previous
#include <cuda_runtime.h>
#include <cuda_fp16.h>
#include <cstdint>

#define HID 256
#define LC 512
#define NCH 256
#define PLANE (HID*LC)

// Activation ping-pong buffers: packed (hi,lo) half2 per element, or fp32 at the ends.
__device__ float g_bufA[(size_t)NCH * PLANE];
__device__ float g_bufB[(size_t)NCH * PLANE];

// Fragment-layout weights: [layer][kt][mtile][lane] -> uint4 (8 halves, mma A-frag order)
__device__ uint4 WC_hi[7 * 48 * 16 * 32];
__device__ uint4 WC_lo[7 * 48 * 16 * 32];
__device__ uint4 WP_hi[18 * 16 * 32];
__device__ uint4 WP_lo[18 * 16 * 32];

// ---------------------------------------------------------------------------
__device__ __forceinline__ uint32_t smem_u32(const void* p) {
    uint32_t a;
    asm("{ .reg .u64 t; cvta.to.shared.u64 t, %1; cvt.u32.u64 %0, t; }" : "=r"(a) : "l"(p));
    return a;
}
__device__ __forceinline__ float gelu_res(float c) {
    return fmaf(0.5f * c, 1.0f + erff(c * 0.70710678118654752440f), c);
}
__device__ __forceinline__ uint32_t pack_hl(float v) {
    __half hh = __float2half_rn(v);
    float res = v - __half2float(hh);
    return (uint32_t)__half_as_ushort(hh) |
           ((uint32_t)__half_as_ushort(__float2half_rn(res)) << 16);
}
__device__ __forceinline__ void mma16816(float* d, const uint4 a, uint32_t b0, uint32_t b1) {
    asm volatile(
        "mma.sync.aligned.m16n8k16.row.col.f32.f16.f16.f32 "
        "{%0,%1,%2,%3}, {%4,%5,%6,%7}, {%8,%9}, {%0,%1,%2,%3};"
        : "+f"(d[0]), "+f"(d[1]), "+f"(d[2]), "+f"(d[3])
        : "r"(a.x), "r"(a.y), "r"(a.z), "r"(a.w), "r"(b0), "r"(b1));
}
__device__ __forceinline__ void ldmx4(uint32_t& r0, uint32_t& r1, uint32_t& r2, uint32_t& r3,
                                      uint32_t addr) {
    asm volatile("ldmatrix.sync.aligned.m8n8.x4.shared.b16 {%0,%1,%2,%3}, [%4];"
                 : "=r"(r0), "=r"(r1), "=r"(r2), "=r"(r3) : "r"(addr));
}
__device__ __forceinline__ void ldmx4t(uint32_t& r0, uint32_t& r1, uint32_t& r2, uint32_t& r3,
                                       uint32_t addr) {
    asm volatile("ldmatrix.sync.aligned.m8n8.x4.trans.shared.b16 {%0,%1,%2,%3}, [%4];"
                 : "=r"(r0), "=r"(r1), "=r"(r2), "=r"(r3) : "r"(addr));
}
__device__ __forceinline__ uint4 lds128(uint32_t addr) {
    uint4 r;
    asm volatile("ld.shared.v4.u32 {%0,%1,%2,%3}, [%4];"
                 : "=r"(r.x), "=r"(r.y), "=r"(r.z), "=r"(r.w) : "r"(addr));
    return r;
}
__device__ __forceinline__ void cp16(uint32_t dst, const void* src) {
    asm volatile("cp.async.cg.shared.global [%0], [%1], 16;" :: "r"(dst), "l"(src));
}
#define CP_COMMIT() asm volatile("cp.async.commit_group;" ::: "memory")
#define CP_WAIT0()  asm volatile("cp.async.wait_group 0;" ::: "memory")

// ---------------------------------------------------------------------------
// Weight prep: fp32 -> (hi,lo) fp16 in mma A-fragment order.
// ---------------------------------------------------------------------------
__device__ __forceinline__ void split_pack(const float* v, uint4& hi, uint4& lo) {
    uint32_t hx[4], lx[4];
#pragma unroll
    for (int q = 0; q < 4; q++) {
        float a = v[2 * q], b = v[2 * q + 1];
        __half ah = __float2half_rn(a), bh = __float2half_rn(b);
        float ar = a - __half2float(ah), br = b - __half2float(bh);
        hx[q] = (uint32_t)__half_as_ushort(ah) | ((uint32_t)__half_as_ushort(bh) << 16);
        lx[q] = (uint32_t)__half_as_ushort(__float2half_rn(ar)) |
                ((uint32_t)__half_as_ushort(__float2half_rn(br)) << 16);
    }
    hi = make_uint4(hx[0], hx[1], hx[2], hx[3]);
    lo = make_uint4(lx[0], lx[1], lx[2], lx[3]);
}

__global__ void prep_conv_w(const float* __restrict__ tw) {
    int idx = blockIdx.x * 256 + threadIdx.x;
    if (idx >= 7 * 48 * 16 * 32) return;
    int lane = idx & 31;
    int mt = (idx >> 5) & 15;
    int kt = (idx >> 9) % 48;
    int layer = (idx >> 9) / 48;
    int g = lane >> 2, t = lane & 3;
    const float* W = tw + (size_t)layer * 256 * 768;
    int r0 = mt * 16 + g, r1 = r0 + 8;
    int c0 = kt * 16 + 2 * t;
    float v[8];
    v[0] = W[r0 * 768 + c0];     v[1] = W[r0 * 768 + c0 + 1];
    v[2] = W[r1 * 768 + c0];     v[3] = W[r1 * 768 + c0 + 1];
    v[4] = W[r0 * 768 + c0 + 8]; v[5] = W[r0 * 768 + c0 + 9];
    v[6] = W[r1 * 768 + c0 + 8]; v[7] = W[r1 * 768 + c0 + 9];
    split_pack(v, WC_hi[idx], WC_lo[idx]);
}

__global__ void prep_proj_w(const float* __restrict__ wp) {
    int idx = blockIdx.x * 256 + threadIdx.x;
    if (idx >= 18 * 16 * 32) return;
    int lane = idx & 31;
    int mt = (idx >> 5) & 15;
    int kt = idx >> 9;
    int g = lane >> 2, t = lane & 3;
    int r0 = mt * 16 + g, r1 = r0 + 8;
    int c0 = kt * 16 + 2 * t;
    const int cs[4] = {c0, c0 + 1, c0 + 8, c0 + 9};
    float v[8];
    v[0] = (cs[0] < 283) ? wp[r0 * 283 + cs[0]] : 0.f;
    v[1] = (cs[1] < 283) ? wp[r0 * 283 + cs[1]] : 0.f;
    v[2] = (cs[0] < 283) ? wp[r1 * 283 + cs[0]] : 0.f;
    v[3] = (cs[1] < 283) ? wp[r1 * 283 + cs[1]] : 0.f;
    v[4] = (cs[2] < 283) ? wp[r0 * 283 + cs[2]] : 0.f;
    v[5] = (cs[3] < 283) ? wp[r0 * 283 + cs[3]] : 0.f;
    v[6] = (cs[2] < 283) ? wp[r1 * 283 + cs[2]] : 0.f;
    v[7] = (cs[3] < 283) ? wp[r1 * 283 + cs[3]] : 0.f;
    split_pack(v, WP_hi[idx], WP_lo[idx]);
}

// ---------------------------------------------------------------------------
// Projection kernel (validated): C[256co][131072r] = Wp * X^T.
// Writes packed (hi,lo) activations to g_bufA.
// ---------------------------------------------------------------------------
__global__ __launch_bounds__(256, 1) void proj_kernel(const float* __restrict__ xin) {
    constexpr int KT = 18;
    __shared__ unsigned short Bs[2][2][128 * 24];

    const int tid = threadIdx.x;
    const int lane = tid & 31;
    const int wid = tid >> 5;
    const int wm = wid >> 2;
    const int wn = wid & 3;
    const int mbase = blockIdx.y * 128;
    const int rbase = blockIdx.x * 128;

    const int kk = tid & 15;
    const int lrow = tid >> 4;
    uint32_t vr[8];

    auto gather = [&](int kt) {
        int m = kt * 16 + kk;
#pragma unroll
        for (int e = 0; e < 8; e++) {
            float v = 0.f;
            if (m < 283) v = xin[(size_t)(rbase + lrow + e * 16) * 283 + m];
            vr[e] = pack_hl(v);
        }
    };
    auto stsB = [&](int s) {
#pragma unroll
        for (int e = 0; e < 8; e++) {
            int l = lrow + e * 16;
            Bs[s][0][l * 24 + kk] = (unsigned short)(vr[e] & 0xffff);
            Bs[s][1][l * 24 + kk] = (unsigned short)(vr[e] >> 16);
        }
    };

    uint4 Ah[2][4], Al[2][4];
    auto loadA = [&](int kt, int b) {
#pragma unroll
        for (int i = 0; i < 4; i++) {
            int mt = blockIdx.y * 8 + wm * 4 + i;
            size_t o = (size_t)(kt * 16 + mt) * 32 + lane;
            Ah[b][i] = WP_hi[o];
            Al[b][i] = WP_lo[o];
        }
    };

    float acc[4][4][4];
#pragma unroll
    for (int i = 0; i < 4; i++)
#pragma unroll
        for (int j = 0; j < 4; j++)
#pragma unroll
            for (int q = 0; q < 4; q++) acc[i][j][q] = 0.f;

    gather(0); stsB(0); loadA(0, 0);
    __syncthreads();

    const uint32_t sbase = smem_u32(Bs);
    const int rsel = (lane & 7) + ((lane & 16) ? 8 : 0);
    const int csel = (lane & 8) ? 8 : 0;

    auto body = [&](int kt, int s) {
        if (kt + 1 < KT) { gather(kt + 1); loadA(kt + 1, s ^ 1); }
        uint32_t bh[4][2], bl[4][2];
#pragma unroll
        for (int pr = 0; pr < 2; pr++) {
            int row = wn * 32 + pr * 16 + rsel;
            uint32_t ah = sbase + (uint32_t)(((s * 2 + 0) * 3072 + row * 24 + csel) * 2);
            uint32_t al = sbase + (uint32_t)(((s * 2 + 1) * 3072 + row * 24 + csel) * 2);
            uint32_t r0, r1, r2, r3;
            ldmx4(r0, r1, r2, r3, ah);
            bh[pr * 2][0] = r0; bh[pr * 2][1] = r1;
            bh[pr * 2 + 1][0] = r2; bh[pr * 2 + 1][1] = r3;
            ldmx4(r0, r1, r2, r3, al);
            bl[pr * 2][0] = r0; bl[pr * 2][1] = r1;
            bl[pr * 2 + 1][0] = r2; bl[pr * 2 + 1][1] = r3;
        }
#pragma unroll
        for (int i = 0; i < 4; i++)
#pragma unroll
            for (int j = 0; j < 4; j++) {
                mma16816(acc[i][j], Ah[s][i], bh[j][0], bh[j][1]);
                mma16816(acc[i][j], Ah[s][i], bl[j][0], bl[j][1]);
                mma16816(acc[i][j], Al[s][i], bh[j][0], bh[j][1]);
            }
        if (kt + 1 < KT) stsB(s ^ 1);
        __syncthreads();
    };

    for (int kt2 = 0; kt2 < KT; kt2 += 2) { body(kt2, 0); body(kt2 + 1, 1); }

    const int g = lane >> 2, t4 = lane & 3;
    int nn = rbase >> 9;
    int lp0 = rbase & 511;
    uint32_t* outp = (uint32_t*)g_bufA + (size_t)nn * PLANE;
#pragma unroll
    for (int i = 0; i < 4; i++) {
        int co0 = mbase + wm * 64 + i * 16 + g;
#pragma unroll
        for (int j = 0; j < 4; j++) {
            int lp = lp0 + wn * 32 + j * 8 + 2 * t4;
            uint2 v0, v1;
            v0.x = pack_hl(acc[i][j][0]); v0.y = pack_hl(acc[i][j][1]);
            v1.x = pack_hl(acc[i][j][2]); v1.y = pack_hl(acc[i][j][3]);
            *(uint2*)&outp[(size_t)co0 * 512 + lp] = v0;
            *(uint2*)&outp[(size_t)(co0 + 8) * 512 + lp] = v1;
        }
    }
}

// ---------------------------------------------------------------------------
// Conv layer kernel (R6 champion + reordered gathers + PRMT repack).
// warp tile 64x32, CTA tile 128(M) x 128(N), 8 warps, 2 CTAs/SM.
// cp.async A pipeline + 4-slot B ring (1 barrier / 2 kt).
// MODE 1: packed half2 out; MODE 2: fp32 out (last layer). gelu+res epilogue.
// ---------------------------------------------------------------------------
#define SSTR 136                 // halves per k-row (128 + 8 pad)
#define A_REG 32768
#define B_PLANE 4352
#define SMEM_CONV (A_REG + 8 * B_PLANE)

__device__ __forceinline__ uint2 ld2_guard(const uint32_t* row, int base) {
    if ((unsigned)base <= 510u) return *(const uint2*)(row + base);
    uint2 r;
    r.x = ((unsigned)(base)     < 512u) ? row[base]     : 0u;
    r.y = ((unsigned)(base + 1) < 512u) ? row[base + 1] : 0u;
    return r;
}

template <int MODE, bool A2B>
__global__ __launch_bounds__(256, 2) void conv_kernel(
    const float* __restrict__ bias, int dil, int layer)
{
    extern __shared__ char dsm[];
    const uint32_t sm0 = smem_u32(dsm);
    const uint32_t sA = sm0;                 // A slots
    const uint32_t sB = sm0 + A_REG;         // B planes
    char* bptr = dsm + A_REG;

    const int tid = threadIdx.x;
    const int lane = tid & 31;
    const int wid = tid >> 5;
    const int wm = wid >> 2;      // 0..1
    const int wn = wid & 3;       // 0..3
    const int mbase = blockIdx.y * 128;
    const int mt8 = blockIdx.y * 8;
    const int n = blockIdx.z;
    const int l0 = blockIdx.x * 128;

    const uint4* __restrict__ WAhi = WC_hi + (size_t)layer * 48 * 16 * 32;
    const uint4* __restrict__ WAlo = WC_lo + (size_t)layer * 48 * 16 * 32;
    const uint32_t* __restrict__ inw =
        (const uint32_t*)(A2B ? g_bufA : g_bufB) + (size_t)n * PLANE;

    // A cp.async: 256 threads x (hi 16B + lo 16B) per kt
    const int amt = tid >> 5;                  // 0..7 local mtile
    auto cpA = [&](int kt, int q) {
        size_t src = (size_t)(kt * 16 + mt8 + amt) * 32 + lane;
        uint32_t d = sA + q * 8192 + tid * 16;
        cp16(d, WAhi + src);
        cp16(d + 4096, WAlo + src);
    };

    // B gather: thread -> (k-row kk, 8 consecutive l at ll0)
    const int kk = tid >> 4;
    const int ll0 = (tid & 15) * 8;
    auto gather = [&](int kt, uint2* v) {
        int kg = kt * 16 + kk;
        int ci = kg / 3;
        int sh = (kg - 3 * ci - 1) * dil;
        const uint32_t* rowp = inw + ci * 512;
        int base = l0 + ll0 + sh;
        v[0] = ld2_guard(rowp, base);
        v[1] = ld2_guard(rowp, base + 2);
        v[2] = ld2_guard(rowp, base + 4);
        v[3] = ld2_guard(rowp, base + 6);
    };
    auto stsB = [&](int q, const uint2* v) {
        uint4 hv, lv;
        hv.x = __byte_perm(v[0].x, v[0].y, 0x5410);
        hv.y = __byte_perm(v[1].x, v[1].y, 0x5410);
        hv.z = __byte_perm(v[2].x, v[2].y, 0x5410);
        hv.w = __byte_perm(v[3].x, v[3].y, 0x5410);
        lv.x = __byte_perm(v[0].x, v[0].y, 0x7632);
        lv.y = __byte_perm(v[1].x, v[1].y, 0x7632);
        lv.z = __byte_perm(v[2].x, v[2].y, 0x7632);
        lv.w = __byte_perm(v[3].x, v[3].y, 0x7632);
        *(uint4*)(bptr + (q * 2 + 0) * B_PLANE + (kk * SSTR + ll0) * 2) = hv;
        *(uint4*)(bptr + (q * 2 + 1) * B_PLANE + (kk * SSTR + ll0) * 2) = lv;
    };

    float acc[4][4][4];
#pragma unroll
    for (int i = 0; i < 4; i++)
#pragma unroll
        for (int j = 0; j < 4; j++)
#pragma unroll
            for (int q = 0; q < 4; q++) acc[i][j][q] = 0.f;

    // ldmatrix.trans lane addressing
    const int grp = lane >> 3, lwi = lane & 7;
    const int krow = (grp & 1) * 8 + lwi;
    const int ncol = wn * 32 + (grp >> 1) * 8;

    auto mma_block = [&](int q) {
        uint32_t ph = sB + (uint32_t)(q * 2 + 0) * B_PLANE;
        uint32_t pl = sB + (uint32_t)(q * 2 + 1) * B_PLANE;
        uint32_t bh[4][2], bl[4][2];
#pragma unroll
        for (int jj = 0; jj < 2; jj++) {
            uint32_t r0, r1, r2, r3;
            ldmx4t(r0, r1, r2, r3, ph + (uint32_t)((krow * SSTR + ncol + jj * 16) * 2));
            bh[jj * 2][0] = r0;     bh[jj * 2][1] = r1;
            bh[jj * 2 + 1][0] = r2; bh[jj * 2 + 1][1] = r3;
            ldmx4t(r0, r1, r2, r3, pl + (uint32_t)((krow * SSTR + ncol + jj * 16) * 2));
            bl[jj * 2][0] = r0;     bl[jj * 2][1] = r1;
            bl[jj * 2 + 1][0] = r2; bl[jj * 2 + 1][1] = r3;
        }
        uint32_t abase = sA + (uint32_t)q * 8192;
#pragma unroll
        for (int ih = 0; ih < 4; ih += 2) {
            uint4 Ah[2], Al[2];
#pragma unroll
            for (int u = 0; u < 2; u++) {
                uint32_t ao = abase + (uint32_t)(((wm * 4 + ih + u) * 32 + lane) * 16);
                Ah[u] = lds128(ao);
                Al[u] = lds128(ao + 4096);
            }
#pragma unroll
            for (int u = 0; u < 2; u++)
#pragma unroll
                for (int j = 0; j < 4; j++) {
                    mma16816(acc[ih + u][j], Ah[u], bh[j][0], bh[j][1]);
                    mma16816(acc[ih + u][j], Ah[u], bl[j][0], bl[j][1]);
                    mma16816(acc[ih + u][j], Al[u], bh[j][0], bh[j][1]);
                }
        }
    };

    // prologue: fill slots 0,1
    uint2 va[4], vb[4];
    cpA(0, 0); cpA(1, 1); CP_COMMIT();
    gather(0, va); stsB(0, va);
    gather(1, vb); stsB(1, vb);
    CP_WAIT0();
    __syncthreads();

    int qc = 0;
    for (int kt2 = 0; kt2 < 48; kt2 += 2) {
        const int qn = qc ^ 2;
        const bool more = (kt2 + 2) < 48;
        if (more) { cpA(kt2 + 2, qn); cpA(kt2 + 3, qn + 1); CP_COMMIT(); }
        if (more) gather(kt2 + 2, va);
        mma_block(qc);
        if (more) gather(kt2 + 3, vb);   // issue BEFORE stsB(qn): longer LDG window
        if (more) stsB(qn, va);
        mma_block(qc + 1);
        if (more) stsB(qn + 1, vb);
        CP_WAIT0();
        __syncthreads();
        qc = qn;
    }

    // ---- epilogue ----
    const int g = lane >> 2, t4 = lane & 3;
    if (MODE == 1) {
        uint32_t* outp = (uint32_t*)(A2B ? g_bufB : g_bufA) + (size_t)n * PLANE;
#pragma unroll
        for (int i = 0; i < 4; i++) {
            int co0 = mbase + wm * 64 + i * 16 + g;
            float b0 = bias[co0], b1 = bias[co0 + 8];
#pragma unroll
            for (int j = 0; j < 4; j++) {
                int lp = l0 + wn * 32 + j * 8 + 2 * t4;
                uint2 v0, v1;
                v0.x = pack_hl(gelu_res(acc[i][j][0] + b0));
                v0.y = pack_hl(gelu_res(acc[i][j][1] + b0));
                v1.x = pack_hl(gelu_res(acc[i][j][2] + b1));
                v1.y = pack_hl(gelu_res(acc[i][j][3] + b1));
                *(uint2*)&outp[(size_t)co0 * 512 + lp] = v0;
                *(uint2*)&outp[(size_t)(co0 + 8) * 512 + lp] = v1;
            }
        }
    } else {
        float* outp = (A2B ? g_bufB : g_bufA) + (size_t)n * PLANE;
#pragma unroll
        for (int i = 0; i < 4; i++) {
            int co0 = mbase + wm * 64 + i * 16 + g;
            float b0 = bias[co0], b1 = bias[co0 + 8];
#pragma unroll
            for (int j = 0; j < 4; j++) {
                int lp = l0 + wn * 32 + j * 8 + 2 * t4;
                float2 v0, v1;
                v0.x = gelu_res(acc[i][j][0] + b0);
                v0.y = gelu_res(acc[i][j][1] + b0);
                v1.x = gelu_res(acc[i][j][2] + b1);
                v1.y = gelu_res(acc[i][j][3] + b1);
                *(float2*)&outp[(size_t)co0 * 512 + lp] = v0;
                *(float2*)&outp[(size_t)(co0 + 8) * 512 + lp] = v1;
            }
        }
    }
}

// ---------------------------------------------------------------------------
// Head: profile conv (K=20, pad (9,10)) + mean pool + atpm, fused.
// ---------------------------------------------------------------------------
__global__ __launch_bounds__(512) void head_kernel(const float* __restrict__ wprof,
                                                   const float* __restrict__ bprof,
                                                   const float* __restrict__ watpm,
                                                   const float* __restrict__ batpm,
                                                   const int* __restrict__ np_raw,
                                                   float* __restrict__ out) {
    __shared__ float buf[2][544];
    __shared__ float wp[HID * 20];
    __shared__ float wa[HID];
    __shared__ float red[16];

    const int n = blockIdx.x;
    const int tid = threadIdx.x;
    const float* h = g_bufB + (size_t)n * PLANE;

    for (int i = tid; i < HID * 20; i += 512) wp[i] = wprof[i];
    if (tid < HID) wa[tid] = watpm[tid];
    if (tid < 9)  { buf[0][tid] = 0.f; buf[1][tid] = 0.f; }
    if (tid < 13) { buf[0][521 + tid] = 0.f; buf[1][521 + tid] = 0.f; }

    float accp = 0.f, acca = 0.f;
    buf[0][9 + tid] = h[tid];
    __syncthreads();

    for (int c = 0; c < HID; c++) {
        const int cur = c & 1;
        if (c + 1 < HID) buf[cur ^ 1][9 + tid] = h[(c + 1) * LC + tid];
        acca = fmaf(buf[cur][9 + tid], wa[c], acca);
        const float* wr = &wp[c * 20];
#pragma unroll
        for (int k = 0; k < 20; k++)
            accp = fmaf(buf[cur][tid + k], wr[k], accp);
        __syncthreads();
    }

    out[256 + n * LC + tid] = accp + bprof[0];

#pragma unroll
    for (int o = 16; o > 0; o >>= 1) acca += __shfl_xor_sync(0xffffffffu, acca, o);
    if ((tid & 31) == 0) red[tid >> 5] = acca;
    __syncthreads();
    if (tid < 16) {
        float vv = red[tid];
#pragma unroll
        for (int o = 8; o > 0; o >>= 1) vv += __shfl_xor_sync(0x0000ffffu, vv, o);
        if (tid == 0) {
            int n0 = np_raw[0];
            int n1;
            int w1 = np_raw[1];
            if (w1 != 0) {
                n1 = w1;
            } else {
                int w2 = np_raw[2], w3 = np_raw[3];
                n1 = (w2 >= 0 && w2 < 128 && w3 == 0) ? w2 : 0;
            }
            float atpm = vv * (1.0f / 512.0f) + batpm[0];
            int p = n & 127, b = n >> 7;
            int lim = (b == 0) ? n0 : n1;
            out[n] = (p < lim) ? atpm : 0.f;
        }
    }
}

// ---------------------------------------------------------------------------
extern "C" void kernel_launch(void* const* d_in, const int* in_sizes, int n_in,
                              void* d_out, int out_size) {
    const float* x       = (const float*)d_in[0];
    const float* w_proj  = (const float*)d_in[1];
    const float* tower_w = (const float*)d_in[2];
    const float* tower_b = (const float*)d_in[3];
    const float* w_prof  = (const float*)d_in[4];
    const float* b_prof  = (const float*)d_in[5];
    const float* w_atpm  = (const float*)d_in[6];
    const float* b_atpm  = (const float*)d_in[7];
    const int*   n_peaks = (const int*)d_in[8];
    float* out = (float*)d_out;

    (void)in_sizes; (void)n_in; (void)out_size;

    cudaFuncSetAttribute(conv_kernel<1, true>,
                         cudaFuncAttributeMaxDynamicSharedMemorySize, SMEM_CONV);
    cudaFuncSetAttribute(conv_kernel<1, false>,
                         cudaFuncAttributeMaxDynamicSharedMemorySize, SMEM_CONV);
    cudaFuncSetAttribute(conv_kernel<2, true>,
                         cudaFuncAttributeMaxDynamicSharedMemorySize, SMEM_CONV);

    // 0) weight prep (fragment layout + fp16 hi/lo split)
    prep_conv_w<<<672, 256>>>(tower_w);
    prep_proj_w<<<36, 256>>>(w_proj);

    // 1) projection -> g_bufA (packed half2 hi/lo)
    proj_kernel<<<dim3(1024, 2, 1), 256>>>(x);

    // 2) conv tower, ping-pong; layer 6 writes fp32 into g_bufB
    dim3 gc(4, 2, NCH);
    for (int i = 0; i < 7; i++) {
        int dil = 2 << i;
        const float* bl = tower_b + (size_t)i * HID;
        if (i == 6)            conv_kernel<2, true ><<<gc, 256, SMEM_CONV>>>(bl, dil, i);
        else if ((i & 1) == 0) conv_kernel<1, true ><<<gc, 256, SMEM_CONV>>>(bl, dil, i);
        else                   conv_kernel<1, false><<<gc, 256, SMEM_CONV>>>(bl, dil, i);
    }

    // 3) fused heads from g_bufB
    head_kernel<<<NCH, 512>>>(w_prof, b_prof, w_atpm, b_atpm, n_peaks, out);
}

// round 9
// speedup vs baseline: 1.2104x; 1.0752x over previous
#include <cuda_runtime.h>
#include <cuda_fp16.h>
#include <cstdint>

#define HID 256
#define LC 512
#define NCH 256
#define PLANE (HID*LC)
#define PR 768                         // padded row: 128 | 512 | 128 halves
#define CBUF ((size_t)NCH * HID * PR)  // halves per activation buffer plane

// Split activation planes (hi fp16 / lo fp16), 2 ping-pong buffers each.
// Zero-initialized (BSS) -> pads stay zero forever; nothing ever writes them.
__device__ unsigned short gPH[2 * CBUF];
__device__ unsigned short gPL[2 * CBUF];
// Final-layer fp32 activations for the head.
__device__ float g_out[(size_t)NCH * PLANE];

// Fragment-layout weights: [layer][kt][mtile][lane] -> uint4 (8 halves, mma A-frag order)
__device__ uint4 WC_hi[7 * 48 * 16 * 32];
__device__ uint4 WC_lo[7 * 48 * 16 * 32];
__device__ uint4 WP_hi[18 * 16 * 32];
__device__ uint4 WP_lo[18 * 16 * 32];

// ---------------------------------------------------------------------------
__device__ __forceinline__ uint32_t smem_u32(const void* p) {
    uint32_t a;
    asm("{ .reg .u64 t; cvta.to.shared.u64 t, %1; cvt.u32.u64 %0, t; }" : "=r"(a) : "l"(p));
    return a;
}
__device__ __forceinline__ float gelu_res(float c) {
    return fmaf(0.5f * c, 1.0f + erff(c * 0.70710678118654752440f), c);
}
__device__ __forceinline__ uint32_t pack_hl(float v) {
    __half hh = __float2half_rn(v);
    float res = v - __half2float(hh);
    return (uint32_t)__half_as_ushort(hh) |
           ((uint32_t)__half_as_ushort(__float2half_rn(res)) << 16);
}
// two values -> packed hi-pair word and lo-pair word
__device__ __forceinline__ void pack2(float a, float b, uint32_t& hi, uint32_t& lo) {
    __half ah = __float2half_rn(a), bh = __float2half_rn(b);
    float ar = a - __half2float(ah), br = b - __half2float(bh);
    hi = (uint32_t)__half_as_ushort(ah) | ((uint32_t)__half_as_ushort(bh) << 16);
    lo = (uint32_t)__half_as_ushort(__float2half_rn(ar)) |
         ((uint32_t)__half_as_ushort(__float2half_rn(br)) << 16);
}
__device__ __forceinline__ void mma16816(float* d, const uint4 a, uint32_t b0, uint32_t b1) {
    asm volatile(
        "mma.sync.aligned.m16n8k16.row.col.f32.f16.f16.f32 "
        "{%0,%1,%2,%3}, {%4,%5,%6,%7}, {%8,%9}, {%0,%1,%2,%3};"
        : "+f"(d[0]), "+f"(d[1]), "+f"(d[2]), "+f"(d[3])
        : "r"(a.x), "r"(a.y), "r"(a.z), "r"(a.w), "r"(b0), "r"(b1));
}
__device__ __forceinline__ void ldmx4(uint32_t& r0, uint32_t& r1, uint32_t& r2, uint32_t& r3,
                                      uint32_t addr) {
    asm volatile("ldmatrix.sync.aligned.m8n8.x4.shared.b16 {%0,%1,%2,%3}, [%4];"
                 : "=r"(r0), "=r"(r1), "=r"(r2), "=r"(r3) : "r"(addr));
}
__device__ __forceinline__ void ldmx4t(uint32_t& r0, uint32_t& r1, uint32_t& r2, uint32_t& r3,
                                       uint32_t addr) {
    asm volatile("ldmatrix.sync.aligned.m8n8.x4.trans.shared.b16 {%0,%1,%2,%3}, [%4];"
                 : "=r"(r0), "=r"(r1), "=r"(r2), "=r"(r3) : "r"(addr));
}
__device__ __forceinline__ uint4 lds128(uint32_t addr) {
    uint4 r;
    asm volatile("ld.shared.v4.u32 {%0,%1,%2,%3}, [%4];"
                 : "=r"(r.x), "=r"(r.y), "=r"(r.z), "=r"(r.w) : "r"(addr));
    return r;
}
__device__ __forceinline__ void cp16(uint32_t dst, const void* src) {
    asm volatile("cp.async.cg.shared.global [%0], [%1], 16;" :: "r"(dst), "l"(src));
}
__device__ __forceinline__ void cp8(uint32_t dst, const void* src) {
    asm volatile("cp.async.ca.shared.global [%0], [%1], 8;" :: "r"(dst), "l"(src));
}
__device__ __forceinline__ void cp4(uint32_t dst, const void* src) {
    asm volatile("cp.async.ca.shared.global [%0], [%1], 4;" :: "r"(dst), "l"(src));
}
#define CP_COMMIT() asm volatile("cp.async.commit_group;" ::: "memory")
#define CP_WAIT0()  asm volatile("cp.async.wait_group 0;" ::: "memory")

// ---------------------------------------------------------------------------
// Weight prep: fp32 -> (hi,lo) fp16 in mma A-fragment order.
// ---------------------------------------------------------------------------
__device__ __forceinline__ void split_pack(const float* v, uint4& hi, uint4& lo) {
    uint32_t hx[4], lx[4];
#pragma unroll
    for (int q = 0; q < 4; q++) {
        pack2(v[2 * q], v[2 * q + 1], hx[q], lx[q]);
    }
    hi = make_uint4(hx[0], hx[1], hx[2], hx[3]);
    lo = make_uint4(lx[0], lx[1], lx[2], lx[3]);
}

__global__ void prep_conv_w(const float* __restrict__ tw) {
    int idx = blockIdx.x * 256 + threadIdx.x;
    if (idx >= 7 * 48 * 16 * 32) return;
    int lane = idx & 31;
    int mt = (idx >> 5) & 15;
    int kt = (idx >> 9) % 48;
    int layer = (idx >> 9) / 48;
    int g = lane >> 2, t = lane & 3;
    const float* W = tw + (size_t)layer * 256 * 768;
    int r0 = mt * 16 + g, r1 = r0 + 8;
    int c0 = kt * 16 + 2 * t;
    float v[8];
    v[0] = W[r0 * 768 + c0];     v[1] = W[r0 * 768 + c0 + 1];
    v[2] = W[r1 * 768 + c0];     v[3] = W[r1 * 768 + c0 + 1];
    v[4] = W[r0 * 768 + c0 + 8]; v[5] = W[r0 * 768 + c0 + 9];
    v[6] = W[r1 * 768 + c0 + 8]; v[7] = W[r1 * 768 + c0 + 9];
    split_pack(v, WC_hi[idx], WC_lo[idx]);
}

__global__ void prep_proj_w(const float* __restrict__ wp) {
    int idx = blockIdx.x * 256 + threadIdx.x;
    if (idx >= 18 * 16 * 32) return;
    int lane = idx & 31;
    int mt = (idx >> 5) & 15;
    int kt = idx >> 9;
    int g = lane >> 2, t = lane & 3;
    int r0 = mt * 16 + g, r1 = r0 + 8;
    int c0 = kt * 16 + 2 * t;
    const int cs[4] = {c0, c0 + 1, c0 + 8, c0 + 9};
    float v[8];
    v[0] = (cs[0] < 283) ? wp[r0 * 283 + cs[0]] : 0.f;
    v[1] = (cs[1] < 283) ? wp[r0 * 283 + cs[1]] : 0.f;
    v[2] = (cs[0] < 283) ? wp[r1 * 283 + cs[0]] : 0.f;
    v[3] = (cs[1] < 283) ? wp[r1 * 283 + cs[1]] : 0.f;
    v[4] = (cs[2] < 283) ? wp[r0 * 283 + cs[2]] : 0.f;
    v[5] = (cs[3] < 283) ? wp[r0 * 283 + cs[3]] : 0.f;
    v[6] = (cs[2] < 283) ? wp[r1 * 283 + cs[2]] : 0.f;
    v[7] = (cs[3] < 283) ? wp[r1 * 283 + cs[3]] : 0.f;
    split_pack(v, WP_hi[idx], WP_lo[idx]);
}

// ---------------------------------------------------------------------------
// Projection kernel: C[256co][131072r] = Wp * X^T.
// Writes split hi/lo planes into activation buffer 0 (padded layout).
// ---------------------------------------------------------------------------
__global__ __launch_bounds__(256, 1) void proj_kernel(const float* __restrict__ xin) {
    constexpr int KT = 18;
    __shared__ unsigned short Bs[2][2][128 * 24];

    const int tid = threadIdx.x;
    const int lane = tid & 31;
    const int wid = tid >> 5;
    const int wm = wid >> 2;
    const int wn = wid & 3;
    const int mbase = blockIdx.y * 128;
    const int rbase = blockIdx.x * 128;

    const int kk = tid & 15;
    const int lrow = tid >> 4;
    uint32_t vr[8];

    auto gather = [&](int kt) {
        int m = kt * 16 + kk;
#pragma unroll
        for (int e = 0; e < 8; e++) {
            float v = 0.f;
            if (m < 283) v = xin[(size_t)(rbase + lrow + e * 16) * 283 + m];
            vr[e] = pack_hl(v);
        }
    };
    auto stsB = [&](int s) {
#pragma unroll
        for (int e = 0; e < 8; e++) {
            int l = lrow + e * 16;
            Bs[s][0][l * 24 + kk] = (unsigned short)(vr[e] & 0xffff);
            Bs[s][1][l * 24 + kk] = (unsigned short)(vr[e] >> 16);
        }
    };

    uint4 Ah[2][4], Al[2][4];
    auto loadA = [&](int kt, int b) {
#pragma unroll
        for (int i = 0; i < 4; i++) {
            int mt = blockIdx.y * 8 + wm * 4 + i;
            size_t o = (size_t)(kt * 16 + mt) * 32 + lane;
            Ah[b][i] = WP_hi[o];
            Al[b][i] = WP_lo[o];
        }
    };

    float acc[4][4][4];
#pragma unroll
    for (int i = 0; i < 4; i++)
#pragma unroll
        for (int j = 0; j < 4; j++)
#pragma unroll
            for (int q = 0; q < 4; q++) acc[i][j][q] = 0.f;

    gather(0); stsB(0); loadA(0, 0);
    __syncthreads();

    const uint32_t sbase = smem_u32(Bs);
    const int rsel = (lane & 7) + ((lane & 16) ? 8 : 0);
    const int csel = (lane & 8) ? 8 : 0;

    auto body = [&](int kt, int s) {
        if (kt + 1 < KT) { gather(kt + 1); loadA(kt + 1, s ^ 1); }
        uint32_t bh[4][2], bl[4][2];
#pragma unroll
        for (int pr = 0; pr < 2; pr++) {
            int row = wn * 32 + pr * 16 + rsel;
            uint32_t ah = sbase + (uint32_t)(((s * 2 + 0) * 3072 + row * 24 + csel) * 2);
            uint32_t al = sbase + (uint32_t)(((s * 2 + 1) * 3072 + row * 24 + csel) * 2);
            uint32_t r0, r1, r2, r3;
            ldmx4(r0, r1, r2, r3, ah);
            bh[pr * 2][0] = r0; bh[pr * 2][1] = r1;
            bh[pr * 2 + 1][0] = r2; bh[pr * 2 + 1][1] = r3;
            ldmx4(r0, r1, r2, r3, al);
            bl[pr * 2][0] = r0; bl[pr * 2][1] = r1;
            bl[pr * 2 + 1][0] = r2; bl[pr * 2 + 1][1] = r3;
        }
#pragma unroll
        for (int i = 0; i < 4; i++)
#pragma unroll
            for (int j = 0; j < 4; j++) {
                mma16816(acc[i][j], Ah[s][i], bh[j][0], bh[j][1]);
                mma16816(acc[i][j], Ah[s][i], bl[j][0], bl[j][1]);
                mma16816(acc[i][j], Al[s][i], bh[j][0], bh[j][1]);
            }
        if (kt + 1 < KT) stsB(s ^ 1);
        __syncthreads();
    };

    for (int kt2 = 0; kt2 < KT; kt2 += 2) { body(kt2, 0); body(kt2 + 1, 1); }

    const int g = lane >> 2, t4 = lane & 3;
    int nn = rbase >> 9;
    int lp0 = rbase & 511;
#pragma unroll
    for (int i = 0; i < 4; i++) {
        int co0 = mbase + wm * 64 + i * 16 + g;
#pragma unroll
        for (int j = 0; j < 4; j++) {
            int lp = lp0 + wn * 32 + j * 8 + 2 * t4;
            size_t r0i = ((size_t)nn * HID + co0) * PR + 128 + lp;
            size_t r1i = ((size_t)nn * HID + co0 + 8) * PR + 128 + lp;
            uint32_t h01, l01, h23, l23;
            pack2(acc[i][j][0], acc[i][j][1], h01, l01);
            pack2(acc[i][j][2], acc[i][j][3], h23, l23);
            *(uint32_t*)&gPH[r0i] = h01; *(uint32_t*)&gPL[r0i] = l01;
            *(uint32_t*)&gPH[r1i] = h23; *(uint32_t*)&gPL[r1i] = l23;
        }
    }
}

// ---------------------------------------------------------------------------
// Conv layer kernel: all tile data via cp.async (A from frag-weights, B from
// padded split planes — shifts are pure pointer offsets, no guards/repack).
// warp tile 64x32, CTA tile 128(M) x 128(N), 8 warps, 2 CTAs/SM.
// 4-slot ring, 1 barrier / 2 kt. MODE 1: split planes out; MODE 2: fp32 out.
// CSZ = cp.async element size for B (16 for d>=8, 8 for d=4, 4 for d=2).
// ---------------------------------------------------------------------------
#define SSTR 136
#define A_REG 32768
#define B_PLANE 4352
#define SMEM_CONV (A_REG + 8 * B_PLANE)

template <int MODE, int BUF, int CSZ>
__global__ __launch_bounds__(256, 2) void conv_kernel(
    const float* __restrict__ bias, int dil, int layer)
{
    extern __shared__ char dsm[];
    const uint32_t sm0 = smem_u32(dsm);
    const uint32_t sA = sm0;                 // A slots
    const uint32_t sB = sm0 + A_REG;         // B planes

    const int tid = threadIdx.x;
    const int lane = tid & 31;
    const int wid = tid >> 5;
    const int wm = wid >> 2;      // 0..1
    const int wn = wid & 3;       // 0..3
    const int mbase = blockIdx.y * 128;
    const int mt8 = blockIdx.y * 8;
    const int n = blockIdx.z;
    const int l0 = blockIdx.x * 128;

    const uint4* __restrict__ WAhi = WC_hi + (size_t)layer * 48 * 16 * 32;
    const uint4* __restrict__ WAlo = WC_lo + (size_t)layer * 48 * 16 * 32;
    const unsigned short* __restrict__ inH = gPH + (size_t)BUF * CBUF;
    const unsigned short* __restrict__ inL = gPL + (size_t)BUF * CBUF;

    // A cp.async: 256 threads x (hi 16B + lo 16B) per kt
    const int amt = tid >> 5;
    auto cpA = [&](int kt, int q) {
        size_t src = (size_t)(kt * 16 + mt8 + amt) * 32 + lane;
        uint32_t d = sA + q * 8192 + tid * 16;
        cp16(d, WAhi + src);
        cp16(d + 4096, WAlo + src);
    };

    // B cp.async: thread -> (k-row kk, 8 consecutive l at ll0), shifted + padded
    const int kk = tid >> 4;
    const int ll0 = (tid & 15) * 8;
    auto cpB = [&](int kt, int q) {
        int kg = kt * 16 + kk;
        int ci = kg / 3;
        int sh = (kg - 3 * ci - 1) * dil;
        size_t off = ((size_t)n * HID + ci) * PR + 128 + l0 + ll0 + sh;
        const unsigned short* srcH = inH + off;
        const unsigned short* srcL = inL + off;
        uint32_t dH = sB + (uint32_t)(q * 2 + 0) * B_PLANE + (uint32_t)((kk * SSTR + ll0) * 2);
        uint32_t dL = sB + (uint32_t)(q * 2 + 1) * B_PLANE + (uint32_t)((kk * SSTR + ll0) * 2);
        if (CSZ == 16) {
            cp16(dH, srcH);
            cp16(dL, srcL);
        } else if (CSZ == 8) {
            cp8(dH, srcH);     cp8(dH + 8, srcH + 4);
            cp8(dL, srcL);     cp8(dL + 8, srcL + 4);
        } else {
            cp4(dH, srcH);      cp4(dH + 4, srcH + 2);
            cp4(dH + 8, srcH + 4); cp4(dH + 12, srcH + 6);
            cp4(dL, srcL);      cp4(dL + 4, srcL + 2);
            cp4(dL + 8, srcL + 4); cp4(dL + 12, srcL + 6);
        }
    };

    float acc[4][4][4];
#pragma unroll
    for (int i = 0; i < 4; i++)
#pragma unroll
        for (int j = 0; j < 4; j++)
#pragma unroll
            for (int q = 0; q < 4; q++) acc[i][j][q] = 0.f;

    // ldmatrix.trans lane addressing
    const int grp = lane >> 3, lwi = lane & 7;
    const int krow = (grp & 1) * 8 + lwi;
    const int ncol = wn * 32 + (grp >> 1) * 8;

    auto mma_block = [&](int q) {
        uint32_t ph = sB + (uint32_t)(q * 2 + 0) * B_PLANE;
        uint32_t pl = sB + (uint32_t)(q * 2 + 1) * B_PLANE;
        uint32_t bh[4][2], bl[4][2];
#pragma unroll
        for (int jj = 0; jj < 2; jj++) {
            uint32_t r0, r1, r2, r3;
            ldmx4t(r0, r1, r2, r3, ph + (uint32_t)((krow * SSTR + ncol + jj * 16) * 2));
            bh[jj * 2][0] = r0;     bh[jj * 2][1] = r1;
            bh[jj * 2 + 1][0] = r2; bh[jj * 2 + 1][1] = r3;
            ldmx4t(r0, r1, r2, r3, pl + (uint32_t)((krow * SSTR + ncol + jj * 16) * 2));
            bl[jj * 2][0] = r0;     bl[jj * 2][1] = r1;
            bl[jj * 2 + 1][0] = r2; bl[jj * 2 + 1][1] = r3;
        }
        uint32_t abase = sA + (uint32_t)q * 8192;
#pragma unroll
        for (int ih = 0; ih < 4; ih += 2) {
            uint4 Ah[2], Al[2];
#pragma unroll
            for (int u = 0; u < 2; u++) {
                uint32_t ao = abase + (uint32_t)(((wm * 4 + ih + u) * 32 + lane) * 16);
                Ah[u] = lds128(ao);
                Al[u] = lds128(ao + 4096);
            }
#pragma unroll
            for (int u = 0; u < 2; u++)
#pragma unroll
                for (int j = 0; j < 4; j++) {
                    mma16816(acc[ih + u][j], Ah[u], bh[j][0], bh[j][1]);
                    mma16816(acc[ih + u][j], Ah[u], bl[j][0], bl[j][1]);
                    mma16816(acc[ih + u][j], Al[u], bh[j][0], bh[j][1]);
                }
        }
    };

    // prologue: fill slots 0,1
    cpA(0, 0); cpB(0, 0);
    cpA(1, 1); cpB(1, 1);
    CP_COMMIT();
    CP_WAIT0();
    __syncthreads();

    int qc = 0;
    for (int kt2 = 0; kt2 < 48; kt2 += 2) {
        const int qn = qc ^ 2;
        const bool more = (kt2 + 2) < 48;
        if (more) {
            cpA(kt2 + 2, qn);     cpB(kt2 + 2, qn);
            cpA(kt2 + 3, qn + 1); cpB(kt2 + 3, qn + 1);
            CP_COMMIT();
        }
        mma_block(qc);
        mma_block(qc + 1);
        if (more) CP_WAIT0();
        __syncthreads();
        qc = qn;
    }

    // ---- epilogue ----
    const int g = lane >> 2, t4 = lane & 3;
    if (MODE == 1) {
        unsigned short* oH = gPH + (size_t)(1 - BUF) * CBUF;
        unsigned short* oL = gPL + (size_t)(1 - BUF) * CBUF;
#pragma unroll
        for (int i = 0; i < 4; i++) {
            int co0 = mbase + wm * 64 + i * 16 + g;
            float b0 = bias[co0], b1 = bias[co0 + 8];
#pragma unroll
            for (int j = 0; j < 4; j++) {
                int lp = l0 + wn * 32 + j * 8 + 2 * t4;
                size_t r0i = ((size_t)n * HID + co0) * PR + 128 + lp;
                size_t r1i = ((size_t)n * HID + co0 + 8) * PR + 128 + lp;
                uint32_t h01, l01, h23, l23;
                pack2(gelu_res(acc[i][j][0] + b0), gelu_res(acc[i][j][1] + b0), h01, l01);
                pack2(gelu_res(acc[i][j][2] + b1), gelu_res(acc[i][j][3] + b1), h23, l23);
                *(uint32_t*)&oH[r0i] = h01; *(uint32_t*)&oL[r0i] = l01;
                *(uint32_t*)&oH[r1i] = h23; *(uint32_t*)&oL[r1i] = l23;
            }
        }
    } else {
#pragma unroll
        for (int i = 0; i < 4; i++) {
            int co0 = mbase + wm * 64 + i * 16 + g;
            float b0 = bias[co0], b1 = bias[co0 + 8];
#pragma unroll
            for (int j = 0; j < 4; j++) {
                int lp = l0 + wn * 32 + j * 8 + 2 * t4;
                float2 v0, v1;
                v0.x = gelu_res(acc[i][j][0] + b0);
                v0.y = gelu_res(acc[i][j][1] + b0);
                v1.x = gelu_res(acc[i][j][2] + b1);
                v1.y = gelu_res(acc[i][j][3] + b1);
                *(float2*)&g_out[(size_t)n * PLANE + (size_t)co0 * 512 + lp] = v0;
                *(float2*)&g_out[(size_t)n * PLANE + (size_t)(co0 + 8) * 512 + lp] = v1;
            }
        }
    }
}

// ---------------------------------------------------------------------------
// Head: profile conv (K=20, pad (9,10)) + mean pool + atpm, fused.
// ---------------------------------------------------------------------------
__global__ __launch_bounds__(512) void head_kernel(const float* __restrict__ wprof,
                                                   const float* __restrict__ bprof,
                                                   const float* __restrict__ watpm,
                                                   const float* __restrict__ batpm,
                                                   const int* __restrict__ np_raw,
                                                   float* __restrict__ out) {
    __shared__ float buf[2][544];
    __shared__ float wp[HID * 20];
    __shared__ float wa[HID];
    __shared__ float red[16];

    const int n = blockIdx.x;
    const int tid = threadIdx.x;
    const float* h = g_out + (size_t)n * PLANE;

    for (int i = tid; i < HID * 20; i += 512) wp[i] = wprof[i];
    if (tid < HID) wa[tid] = watpm[tid];
    if (tid < 9)  { buf[0][tid] = 0.f; buf[1][tid] = 0.f; }
    if (tid < 13) { buf[0][521 + tid] = 0.f; buf[1][521 + tid] = 0.f; }

    float accp = 0.f, acca = 0.f;
    buf[0][9 + tid] = h[tid];
    __syncthreads();

    for (int c = 0; c < HID; c++) {
        const int cur = c & 1;
        if (c + 1 < HID) buf[cur ^ 1][9 + tid] = h[(c + 1) * LC + tid];
        acca = fmaf(buf[cur][9 + tid], wa[c], acca);
        const float* wr = &wp[c * 20];
#pragma unroll
        for (int k = 0; k < 20; k++)
            accp = fmaf(buf[cur][tid + k], wr[k], accp);
        __syncthreads();
    }

    out[256 + n * LC + tid] = accp + bprof[0];

#pragma unroll
    for (int o = 16; o > 0; o >>= 1) acca += __shfl_xor_sync(0xffffffffu, acca, o);
    if ((tid & 31) == 0) red[tid >> 5] = acca;
    __syncthreads();
    if (tid < 16) {
        float vv = red[tid];
#pragma unroll
        for (int o = 8; o > 0; o >>= 1) vv += __shfl_xor_sync(0x0000ffffu, vv, o);
        if (tid == 0) {
            int n0 = np_raw[0];
            int n1;
            int w1 = np_raw[1];
            if (w1 != 0) {
                n1 = w1;
            } else {
                int w2 = np_raw[2], w3 = np_raw[3];
                n1 = (w2 >= 0 && w2 < 128 && w3 == 0) ? w2 : 0;
            }
            float atpm = vv * (1.0f / 512.0f) + batpm[0];
            int p = n & 127, b = n >> 7;
            int lim = (b == 0) ? n0 : n1;
            out[n] = (p < lim) ? atpm : 0.f;
        }
    }
}

// ---------------------------------------------------------------------------
extern "C" void kernel_launch(void* const* d_in, const int* in_sizes, int n_in,
                              void* d_out, int out_size) {
    const float* x       = (const float*)d_in[0];
    const float* w_proj  = (const float*)d_in[1];
    const float* tower_w = (const float*)d_in[2];
    const float* tower_b = (const float*)d_in[3];
    const float* w_prof  = (const float*)d_in[4];
    const float* b_prof  = (const float*)d_in[5];
    const float* w_atpm  = (const float*)d_in[6];
    const float* b_atpm  = (const float*)d_in[7];
    const int*   n_peaks = (const int*)d_in[8];
    float* out = (float*)d_out;

    (void)in_sizes; (void)n_in; (void)out_size;

    cudaFuncSetAttribute(conv_kernel<1, 0, 4>,
                         cudaFuncAttributeMaxDynamicSharedMemorySize, SMEM_CONV);
    cudaFuncSetAttribute(conv_kernel<1, 1, 8>,
                         cudaFuncAttributeMaxDynamicSharedMemorySize, SMEM_CONV);
    cudaFuncSetAttribute(conv_kernel<1, 0, 16>,
                         cudaFuncAttributeMaxDynamicSharedMemorySize, SMEM_CONV);
    cudaFuncSetAttribute(conv_kernel<1, 1, 16>,
                         cudaFuncAttributeMaxDynamicSharedMemorySize, SMEM_CONV);
    cudaFuncSetAttribute(conv_kernel<2, 0, 16>,
                         cudaFuncAttributeMaxDynamicSharedMemorySize, SMEM_CONV);

    // 0) weight prep (fragment layout + fp16 hi/lo split)
    prep_conv_w<<<672, 256>>>(tower_w);
    prep_proj_w<<<36, 256>>>(w_proj);

    // 1) projection -> split planes, buffer 0
    proj_kernel<<<dim3(1024, 2, 1), 256>>>(x);

    // 2) conv tower, ping-pong buffers; layer 6 writes fp32 into g_out
    dim3 gc(4, 2, NCH);
    const float* bl;
    bl = tower_b + 0 * HID; conv_kernel<1, 0, 4 ><<<gc, 256, SMEM_CONV>>>(bl, 2,   0);
    bl = tower_b + 1 * HID; conv_kernel<1, 1, 8 ><<<gc, 256, SMEM_CONV>>>(bl, 4,   1);
    bl = tower_b + 2 * HID; conv_kernel<1, 0, 16><<<gc, 256, SMEM_CONV>>>(bl, 8,   2);
    bl = tower_b + 3 * HID; conv_kernel<1, 1, 16><<<gc, 256, SMEM_CONV>>>(bl, 16,  3);
    bl = tower_b + 4 * HID; conv_kernel<1, 0, 16><<<gc, 256, SMEM_CONV>>>(bl, 32,  4);
    bl = tower_b + 5 * HID; conv_kernel<1, 1, 16><<<gc, 256, SMEM_CONV>>>(bl, 64,  5);
    bl = tower_b + 6 * HID; conv_kernel<2, 0, 16><<<gc, 256, SMEM_CONV>>>(bl, 128, 6);

    // 3) fused heads from g_out
    head_kernel<<<NCH, 512>>>(w_prof, b_prof, w_atpm, b_atpm, n_peaks, out);
}

// round 10
// speedup vs baseline: 1.2242x; 1.0114x over previous
#include <cuda_runtime.h>
#include <cuda_fp16.h>
#include <cstdint>

#define HID 256
#define LC 512
#define NCH 256
#define PLANE (HID*LC)
#define PR 768                         // padded row: 128 | 512 | 128 halves
#define CBUF ((size_t)NCH * HID * PR)  // halves per activation buffer plane

// Split activation planes (hi fp16 / lo fp16), 2 ping-pong buffers each.
// Zero-initialized (BSS) -> pads stay zero forever; nothing ever writes them.
__device__ unsigned short gPH[2 * CBUF];
__device__ unsigned short gPL[2 * CBUF];
// Final-layer fp32 activations for the head.
__device__ float g_out[(size_t)NCH * PLANE];

// Fragment-layout weights: [layer][kt][mtile][lane] -> uint4 (8 halves, mma A-frag order)
__device__ uint4 WC_hi[7 * 48 * 16 * 32];
__device__ uint4 WC_lo[7 * 48 * 16 * 32];
__device__ uint4 WP_hi[18 * 16 * 32];
__device__ uint4 WP_lo[18 * 16 * 32];

// ---------------------------------------------------------------------------
__device__ __forceinline__ uint32_t smem_u32(const void* p) {
    uint32_t a;
    asm("{ .reg .u64 t; cvta.to.shared.u64 t, %1; cvt.u32.u64 %0, t; }" : "=r"(a) : "l"(p));
    return a;
}
__device__ __forceinline__ float gelu_res(float c) {
    return fmaf(0.5f * c, 1.0f + erff(c * 0.70710678118654752440f), c);
}
__device__ __forceinline__ uint32_t pack_hl(float v) {
    __half hh = __float2half_rn(v);
    float res = v - __half2float(hh);
    return (uint32_t)__half_as_ushort(hh) |
           ((uint32_t)__half_as_ushort(__float2half_rn(res)) << 16);
}
// two values -> packed hi-pair word and lo-pair word
__device__ __forceinline__ void pack2(float a, float b, uint32_t& hi, uint32_t& lo) {
    __half ah = __float2half_rn(a), bh = __float2half_rn(b);
    float ar = a - __half2float(ah), br = b - __half2float(bh);
    hi = (uint32_t)__half_as_ushort(ah) | ((uint32_t)__half_as_ushort(bh) << 16);
    lo = (uint32_t)__half_as_ushort(__float2half_rn(ar)) |
         ((uint32_t)__half_as_ushort(__float2half_rn(br)) << 16);
}
__device__ __forceinline__ void mma16816(float* d, const uint4 a, uint32_t b0, uint32_t b1) {
    asm volatile(
        "mma.sync.aligned.m16n8k16.row.col.f32.f16.f16.f32 "
        "{%0,%1,%2,%3}, {%4,%5,%6,%7}, {%8,%9}, {%0,%1,%2,%3};"
        : "+f"(d[0]), "+f"(d[1]), "+f"(d[2]), "+f"(d[3])
        : "r"(a.x), "r"(a.y), "r"(a.z), "r"(a.w), "r"(b0), "r"(b1));
}
__device__ __forceinline__ void ldmx4(uint32_t& r0, uint32_t& r1, uint32_t& r2, uint32_t& r3,
                                      uint32_t addr) {
    asm volatile("ldmatrix.sync.aligned.m8n8.x4.shared.b16 {%0,%1,%2,%3}, [%4];"
                 : "=r"(r0), "=r"(r1), "=r"(r2), "=r"(r3) : "r"(addr));
}
__device__ __forceinline__ void ldmx4t(uint32_t& r0, uint32_t& r1, uint32_t& r2, uint32_t& r3,
                                       uint32_t addr) {
    asm volatile("ldmatrix.sync.aligned.m8n8.x4.trans.shared.b16 {%0,%1,%2,%3}, [%4];"
                 : "=r"(r0), "=r"(r1), "=r"(r2), "=r"(r3) : "r"(addr));
}
__device__ __forceinline__ uint4 lds128(uint32_t addr) {
    uint4 r;
    asm volatile("ld.shared.v4.u32 {%0,%1,%2,%3}, [%4];"
                 : "=r"(r.x), "=r"(r.y), "=r"(r.z), "=r"(r.w) : "r"(addr));
    return r;
}
__device__ __forceinline__ void cp16(uint32_t dst, const void* src) {
    asm volatile("cp.async.cg.shared.global [%0], [%1], 16;" :: "r"(dst), "l"(src));
}
__device__ __forceinline__ void cp8(uint32_t dst, const void* src) {
    asm volatile("cp.async.ca.shared.global [%0], [%1], 8;" :: "r"(dst), "l"(src));
}
__device__ __forceinline__ void cp4(uint32_t dst, const void* src) {
    asm volatile("cp.async.ca.shared.global [%0], [%1], 4;" :: "r"(dst), "l"(src));
}
#define CP_COMMIT() asm volatile("cp.async.commit_group;" ::: "memory")
#define CP_WAIT0()  asm volatile("cp.async.wait_group 0;" ::: "memory")
#define CP_WAIT1()  asm volatile("cp.async.wait_group 1;" ::: "memory")

// ---------------------------------------------------------------------------
// Weight prep: fp32 -> (hi,lo) fp16 in mma A-fragment order.
// ---------------------------------------------------------------------------
__device__ __forceinline__ void split_pack(const float* v, uint4& hi, uint4& lo) {
    uint32_t hx[4], lx[4];
#pragma unroll
    for (int q = 0; q < 4; q++) {
        pack2(v[2 * q], v[2 * q + 1], hx[q], lx[q]);
    }
    hi = make_uint4(hx[0], hx[1], hx[2], hx[3]);
    lo = make_uint4(lx[0], lx[1], lx[2], lx[3]);
}

__global__ void prep_conv_w(const float* __restrict__ tw) {
    int idx = blockIdx.x * 256 + threadIdx.x;
    if (idx >= 7 * 48 * 16 * 32) return;
    int lane = idx & 31;
    int mt = (idx >> 5) & 15;
    int kt = (idx >> 9) % 48;
    int layer = (idx >> 9) / 48;
    int g = lane >> 2, t = lane & 3;
    const float* W = tw + (size_t)layer * 256 * 768;
    int r0 = mt * 16 + g, r1 = r0 + 8;
    int c0 = kt * 16 + 2 * t;
    float v[8];
    v[0] = W[r0 * 768 + c0];     v[1] = W[r0 * 768 + c0 + 1];
    v[2] = W[r1 * 768 + c0];     v[3] = W[r1 * 768 + c0 + 1];
    v[4] = W[r0 * 768 + c0 + 8]; v[5] = W[r0 * 768 + c0 + 9];
    v[6] = W[r1 * 768 + c0 + 8]; v[7] = W[r1 * 768 + c0 + 9];
    split_pack(v, WC_hi[idx], WC_lo[idx]);
}

__global__ void prep_proj_w(const float* __restrict__ wp) {
    int idx = blockIdx.x * 256 + threadIdx.x;
    if (idx >= 18 * 16 * 32) return;
    int lane = idx & 31;
    int mt = (idx >> 5) & 15;
    int kt = idx >> 9;
    int g = lane >> 2, t = lane & 3;
    int r0 = mt * 16 + g, r1 = r0 + 8;
    int c0 = kt * 16 + 2 * t;
    const int cs[4] = {c0, c0 + 1, c0 + 8, c0 + 9};
    float v[8];
    v[0] = (cs[0] < 283) ? wp[r0 * 283 + cs[0]] : 0.f;
    v[1] = (cs[1] < 283) ? wp[r0 * 283 + cs[1]] : 0.f;
    v[2] = (cs[0] < 283) ? wp[r1 * 283 + cs[0]] : 0.f;
    v[3] = (cs[1] < 283) ? wp[r1 * 283 + cs[1]] : 0.f;
    v[4] = (cs[2] < 283) ? wp[r0 * 283 + cs[2]] : 0.f;
    v[5] = (cs[3] < 283) ? wp[r0 * 283 + cs[3]] : 0.f;
    v[6] = (cs[2] < 283) ? wp[r1 * 283 + cs[2]] : 0.f;
    v[7] = (cs[3] < 283) ? wp[r1 * 283 + cs[3]] : 0.f;
    split_pack(v, WP_hi[idx], WP_lo[idx]);
}

// ---------------------------------------------------------------------------
// Projection kernel: C[256co][131072r] = Wp * X^T.
// Writes split hi/lo planes into activation buffer 0 (padded layout).
// ---------------------------------------------------------------------------
__global__ __launch_bounds__(256, 1) void proj_kernel(const float* __restrict__ xin) {
    constexpr int KT = 18;
    __shared__ unsigned short Bs[2][2][128 * 24];

    const int tid = threadIdx.x;
    const int lane = tid & 31;
    const int wid = tid >> 5;
    const int wm = wid >> 2;
    const int wn = wid & 3;
    const int mbase = blockIdx.y * 128;
    const int rbase = blockIdx.x * 128;

    const int kk = tid & 15;
    const int lrow = tid >> 4;
    uint32_t vr[8];

    auto gather = [&](int kt) {
        int m = kt * 16 + kk;
#pragma unroll
        for (int e = 0; e < 8; e++) {
            float v = 0.f;
            if (m < 283) v = xin[(size_t)(rbase + lrow + e * 16) * 283 + m];
            vr[e] = pack_hl(v);
        }
    };
    auto stsB = [&](int s) {
#pragma unroll
        for (int e = 0; e < 8; e++) {
            int l = lrow + e * 16;
            Bs[s][0][l * 24 + kk] = (unsigned short)(vr[e] & 0xffff);
            Bs[s][1][l * 24 + kk] = (unsigned short)(vr[e] >> 16);
        }
    };

    uint4 Ah[2][4], Al[2][4];
    auto loadA = [&](int kt, int b) {
#pragma unroll
        for (int i = 0; i < 4; i++) {
            int mt = blockIdx.y * 8 + wm * 4 + i;
            size_t o = (size_t)(kt * 16 + mt) * 32 + lane;
            Ah[b][i] = WP_hi[o];
            Al[b][i] = WP_lo[o];
        }
    };

    float acc[4][4][4];
#pragma unroll
    for (int i = 0; i < 4; i++)
#pragma unroll
        for (int j = 0; j < 4; j++)
#pragma unroll
            for (int q = 0; q < 4; q++) acc[i][j][q] = 0.f;

    gather(0); stsB(0); loadA(0, 0);
    __syncthreads();

    const uint32_t sbase = smem_u32(Bs);
    const int rsel = (lane & 7) + ((lane & 16) ? 8 : 0);
    const int csel = (lane & 8) ? 8 : 0;

    auto body = [&](int kt, int s) {
        if (kt + 1 < KT) { gather(kt + 1); loadA(kt + 1, s ^ 1); }
        uint32_t bh[4][2], bl[4][2];
#pragma unroll
        for (int pr = 0; pr < 2; pr++) {
            int row = wn * 32 + pr * 16 + rsel;
            uint32_t ah = sbase + (uint32_t)(((s * 2 + 0) * 3072 + row * 24 + csel) * 2);
            uint32_t al = sbase + (uint32_t)(((s * 2 + 1) * 3072 + row * 24 + csel) * 2);
            uint32_t r0, r1, r2, r3;
            ldmx4(r0, r1, r2, r3, ah);
            bh[pr * 2][0] = r0; bh[pr * 2][1] = r1;
            bh[pr * 2 + 1][0] = r2; bh[pr * 2 + 1][1] = r3;
            ldmx4(r0, r1, r2, r3, al);
            bl[pr * 2][0] = r0; bl[pr * 2][1] = r1;
            bl[pr * 2 + 1][0] = r2; bl[pr * 2 + 1][1] = r3;
        }
#pragma unroll
        for (int i = 0; i < 4; i++)
#pragma unroll
            for (int j = 0; j < 4; j++) {
                mma16816(acc[i][j], Ah[s][i], bh[j][0], bh[j][1]);
                mma16816(acc[i][j], Ah[s][i], bl[j][0], bl[j][1]);
                mma16816(acc[i][j], Al[s][i], bh[j][0], bh[j][1]);
            }
        if (kt + 1 < KT) stsB(s ^ 1);
        __syncthreads();
    };

    for (int kt2 = 0; kt2 < KT; kt2 += 2) { body(kt2, 0); body(kt2 + 1, 1); }

    const int g = lane >> 2, t4 = lane & 3;
    int nn = rbase >> 9;
    int lp0 = rbase & 511;
#pragma unroll
    for (int i = 0; i < 4; i++) {
        int co0 = mbase + wm * 64 + i * 16 + g;
#pragma unroll
        for (int j = 0; j < 4; j++) {
            int lp = lp0 + wn * 32 + j * 8 + 2 * t4;
            size_t r0i = ((size_t)nn * HID + co0) * PR + 128 + lp;
            size_t r1i = ((size_t)nn * HID + co0 + 8) * PR + 128 + lp;
            uint32_t h01, l01, h23, l23;
            pack2(acc[i][j][0], acc[i][j][1], h01, l01);
            pack2(acc[i][j][2], acc[i][j][3], h23, l23);
            *(uint32_t*)&gPH[r0i] = h01; *(uint32_t*)&gPL[r0i] = l01;
            *(uint32_t*)&gPH[r1i] = h23; *(uint32_t*)&gPL[r1i] = l23;
        }
    }
}

// ---------------------------------------------------------------------------
// Conv layer kernel: all tile data via cp.async; 3-pair (6-slot) ring with
// wait_group 1 -> ~2 iterations of latency-hiding per copy. Commit happens
// AFTER the iteration barrier (slot of pair i+2 == slot of pair i-1, whose
// readers all passed that barrier) -> race-free.
// warp tile 64x32, CTA tile 128(M) x 128(N), 8 warps, 2 CTAs/SM.
// MODE 1: split planes out; MODE 2: fp32 out. CSZ = B cp.async element size.
// ---------------------------------------------------------------------------
#define SSTR 136
#define A_SLOT 8192
#define A_REG (6 * A_SLOT)           // 49152
#define B_PLANE 4352
#define SMEM_CONV (A_REG + 12 * B_PLANE)   // 101376

template <int MODE, int BUF, int CSZ>
__global__ __launch_bounds__(256, 2) void conv_kernel(
    const float* __restrict__ bias, int dil, int layer)
{
    extern __shared__ char dsm[];
    const uint32_t sm0 = smem_u32(dsm);
    const uint32_t sA = sm0;                 // A slots (6)
    const uint32_t sB = sm0 + A_REG;         // B planes (12)

    const int tid = threadIdx.x;
    const int lane = tid & 31;
    const int wid = tid >> 5;
    const int wm = wid >> 2;      // 0..1
    const int wn = wid & 3;       // 0..3
    const int mbase = blockIdx.y * 128;
    const int mt8 = blockIdx.y * 8;
    const int n = blockIdx.z;
    const int l0 = blockIdx.x * 128;

    const uint4* __restrict__ WAhi = WC_hi + (size_t)layer * 48 * 16 * 32;
    const uint4* __restrict__ WAlo = WC_lo + (size_t)layer * 48 * 16 * 32;
    const unsigned short* __restrict__ inH = gPH + (size_t)BUF * CBUF;
    const unsigned short* __restrict__ inL = gPL + (size_t)BUF * CBUF;

    // A cp.async: 256 threads x (hi 16B + lo 16B) per kt
    const int amt = tid >> 5;
    auto cpA = [&](int kt, int q) {
        size_t src = (size_t)(kt * 16 + mt8 + amt) * 32 + lane;
        uint32_t d = sA + q * A_SLOT + tid * 16;
        cp16(d, WAhi + src);
        cp16(d + 4096, WAlo + src);
    };

    // B cp.async: thread -> (k-row kk, 8 consecutive l at ll0), shifted + padded
    const int kk = tid >> 4;
    const int ll0 = (tid & 15) * 8;
    auto cpB = [&](int kt, int q) {
        int kg = kt * 16 + kk;
        int ci = kg / 3;
        int sh = (kg - 3 * ci - 1) * dil;
        size_t off = ((size_t)n * HID + ci) * PR + 128 + l0 + ll0 + sh;
        const unsigned short* srcH = inH + off;
        const unsigned short* srcL = inL + off;
        uint32_t dH = sB + (uint32_t)(q * 2 + 0) * B_PLANE + (uint32_t)((kk * SSTR + ll0) * 2);
        uint32_t dL = sB + (uint32_t)(q * 2 + 1) * B_PLANE + (uint32_t)((kk * SSTR + ll0) * 2);
        if (CSZ == 16) {
            cp16(dH, srcH);
            cp16(dL, srcL);
        } else if (CSZ == 8) {
            cp8(dH, srcH);     cp8(dH + 8, srcH + 4);
            cp8(dL, srcL);     cp8(dL + 8, srcL + 4);
        } else {
            cp4(dH, srcH);      cp4(dH + 4, srcH + 2);
            cp4(dH + 8, srcH + 4); cp4(dH + 12, srcH + 6);
            cp4(dL, srcL);      cp4(dL + 4, srcL + 2);
            cp4(dL + 8, srcL + 4); cp4(dL + 12, srcL + 6);
        }
    };

    float acc[4][4][4];
#pragma unroll
    for (int i = 0; i < 4; i++)
#pragma unroll
        for (int j = 0; j < 4; j++)
#pragma unroll
            for (int q = 0; q < 4; q++) acc[i][j][q] = 0.f;

    // ldmatrix.trans lane addressing
    const int grp = lane >> 3, lwi = lane & 7;
    const int krow = (grp & 1) * 8 + lwi;
    const int ncol = wn * 32 + (grp >> 1) * 8;

    auto mma_block = [&](int q) {
        uint32_t ph = sB + (uint32_t)(q * 2 + 0) * B_PLANE;
        uint32_t pl = sB + (uint32_t)(q * 2 + 1) * B_PLANE;
        uint32_t bh[4][2], bl[4][2];
#pragma unroll
        for (int jj = 0; jj < 2; jj++) {
            uint32_t r0, r1, r2, r3;
            ldmx4t(r0, r1, r2, r3, ph + (uint32_t)((krow * SSTR + ncol + jj * 16) * 2));
            bh[jj * 2][0] = r0;     bh[jj * 2][1] = r1;
            bh[jj * 2 + 1][0] = r2; bh[jj * 2 + 1][1] = r3;
            ldmx4t(r0, r1, r2, r3, pl + (uint32_t)((krow * SSTR + ncol + jj * 16) * 2));
            bl[jj * 2][0] = r0;     bl[jj * 2][1] = r1;
            bl[jj * 2 + 1][0] = r2; bl[jj * 2 + 1][1] = r3;
        }
        uint32_t abase = sA + (uint32_t)q * A_SLOT;
#pragma unroll
        for (int ih = 0; ih < 4; ih += 2) {
            uint4 Ah[2], Al[2];
#pragma unroll
            for (int u = 0; u < 2; u++) {
                uint32_t ao = abase + (uint32_t)(((wm * 4 + ih + u) * 32 + lane) * 16);
                Ah[u] = lds128(ao);
                Al[u] = lds128(ao + 4096);
            }
#pragma unroll
            for (int u = 0; u < 2; u++)
#pragma unroll
                for (int j = 0; j < 4; j++) {
                    mma16816(acc[ih + u][j], Ah[u], bh[j][0], bh[j][1]);
                    mma16816(acc[ih + u][j], Ah[u], bl[j][0], bl[j][1]);
                    mma16816(acc[ih + u][j], Al[u], bh[j][0], bh[j][1]);
                }
        }
    };

    // prologue: pairs 0 (kt 0,1) and 1 (kt 2,3), one commit group each
    cpA(0, 0); cpB(0, 0);
    cpA(1, 1); cpB(1, 1);
    CP_COMMIT();
    cpA(2, 2); cpB(2, 2);
    cpA(3, 3); cpB(3, 3);
    CP_COMMIT();

    for (int kt2 = 0; kt2 < 48; kt2 += 2) {
        const int pr3 = (kt2 >> 1) % 3;          // current pair 0..2
        CP_WAIT1();                               // current pair's group retired
        __syncthreads();                          // all readers of pair (i-1) done
        if (kt2 + 4 < 48) {
            const int pn = pr3 == 0 ? 2 : pr3 - 1;   // (pr3+2)%3
            cpA(kt2 + 4, pn * 2);     cpB(kt2 + 4, pn * 2);
            cpA(kt2 + 5, pn * 2 + 1); cpB(kt2 + 5, pn * 2 + 1);
        }
        CP_COMMIT();                              // commit (possibly empty) group
        mma_block(pr3 * 2);
        mma_block(pr3 * 2 + 1);
    }

    // ---- epilogue ----
    const int g = lane >> 2, t4 = lane & 3;
    if (MODE == 1) {
        unsigned short* oH = gPH + (size_t)(1 - BUF) * CBUF;
        unsigned short* oL = gPL + (size_t)(1 - BUF) * CBUF;
#pragma unroll
        for (int i = 0; i < 4; i++) {
            int co0 = mbase + wm * 64 + i * 16 + g;
            float b0 = bias[co0], b1 = bias[co0 + 8];
#pragma unroll
            for (int j = 0; j < 4; j++) {
                int lp = l0 + wn * 32 + j * 8 + 2 * t4;
                size_t r0i = ((size_t)n * HID + co0) * PR + 128 + lp;
                size_t r1i = ((size_t)n * HID + co0 + 8) * PR + 128 + lp;
                uint32_t h01, l01, h23, l23;
                pack2(gelu_res(acc[i][j][0] + b0), gelu_res(acc[i][j][1] + b0), h01, l01);
                pack2(gelu_res(acc[i][j][2] + b1), gelu_res(acc[i][j][3] + b1), h23, l23);
                *(uint32_t*)&oH[r0i] = h01; *(uint32_t*)&oL[r0i] = l01;
                *(uint32_t*)&oH[r1i] = h23; *(uint32_t*)&oL[r1i] = l23;
            }
        }
    } else {
#pragma unroll
        for (int i = 0; i < 4; i++) {
            int co0 = mbase + wm * 64 + i * 16 + g;
            float b0 = bias[co0], b1 = bias[co0 + 8];
#pragma unroll
            for (int j = 0; j < 4; j++) {
                int lp = l0 + wn * 32 + j * 8 + 2 * t4;
                float2 v0, v1;
                v0.x = gelu_res(acc[i][j][0] + b0);
                v0.y = gelu_res(acc[i][j][1] + b0);
                v1.x = gelu_res(acc[i][j][2] + b1);
                v1.y = gelu_res(acc[i][j][3] + b1);
                *(float2*)&g_out[(size_t)n * PLANE + (size_t)co0 * 512 + lp] = v0;
                *(float2*)&g_out[(size_t)n * PLANE + (size_t)(co0 + 8) * 512 + lp] = v1;
            }
        }
    }
}

// ---------------------------------------------------------------------------
// Head: profile conv (K=20, pad (9,10)) + mean pool + atpm, fused.
// ---------------------------------------------------------------------------
__global__ __launch_bounds__(512) void head_kernel(const float* __restrict__ wprof,
                                                   const float* __restrict__ bprof,
                                                   const float* __restrict__ watpm,
                                                   const float* __restrict__ batpm,
                                                   const int* __restrict__ np_raw,
                                                   float* __restrict__ out) {
    __shared__ float buf[2][544];
    __shared__ float wp[HID * 20];
    __shared__ float wa[HID];
    __shared__ float red[16];

    const int n = blockIdx.x;
    const int tid = threadIdx.x;
    const float* h = g_out + (size_t)n * PLANE;

    for (int i = tid; i < HID * 20; i += 512) wp[i] = wprof[i];
    if (tid < HID) wa[tid] = watpm[tid];
    if (tid < 9)  { buf[0][tid] = 0.f; buf[1][tid] = 0.f; }
    if (tid < 13) { buf[0][521 + tid] = 0.f; buf[1][521 + tid] = 0.f; }

    float accp = 0.f, acca = 0.f;
    buf[0][9 + tid] = h[tid];
    __syncthreads();

    for (int c = 0; c < HID; c++) {
        const int cur = c & 1;
        if (c + 1 < HID) buf[cur ^ 1][9 + tid] = h[(c + 1) * LC + tid];
        acca = fmaf(buf[cur][9 + tid], wa[c], acca);
        const float* wr = &wp[c * 20];
#pragma unroll
        for (int k = 0; k < 20; k++)
            accp = fmaf(buf[cur][tid + k], wr[k], accp);
        __syncthreads();
    }

    out[256 + n * LC + tid] = accp + bprof[0];

#pragma unroll
    for (int o = 16; o > 0; o >>= 1) acca += __shfl_xor_sync(0xffffffffu, acca, o);
    if ((tid & 31) == 0) red[tid >> 5] = acca;
    __syncthreads();
    if (tid < 16) {
        float vv = red[tid];
#pragma unroll
        for (int o = 8; o > 0; o >>= 1) vv += __shfl_xor_sync(0x0000ffffu, vv, o);
        if (tid == 0) {
            int n0 = np_raw[0];
            int n1;
            int w1 = np_raw[1];
            if (w1 != 0) {
                n1 = w1;
            } else {
                int w2 = np_raw[2], w3 = np_raw[3];
                n1 = (w2 >= 0 && w2 < 128 && w3 == 0) ? w2 : 0;
            }
            float atpm = vv * (1.0f / 512.0f) + batpm[0];
            int p = n & 127, b = n >> 7;
            int lim = (b == 0) ? n0 : n1;
            out[n] = (p < lim) ? atpm : 0.f;
        }
    }
}

// ---------------------------------------------------------------------------
extern "C" void kernel_launch(void* const* d_in, const int* in_sizes, int n_in,
                              void* d_out, int out_size) {
    const float* x       = (const float*)d_in[0];
    const float* w_proj  = (const float*)d_in[1];
    const float* tower_w = (const float*)d_in[2];
    const float* tower_b = (const float*)d_in[3];
    const float* w_prof  = (const float*)d_in[4];
    const float* b_prof  = (const float*)d_in[5];
    const float* w_atpm  = (const float*)d_in[6];
    const float* b_atpm  = (const float*)d_in[7];
    const int*   n_peaks = (const int*)d_in[8];
    float* out = (float*)d_out;

    (void)in_sizes; (void)n_in; (void)out_size;

    cudaFuncSetAttribute(conv_kernel<1, 0, 4>,
                         cudaFuncAttributeMaxDynamicSharedMemorySize, SMEM_CONV);
    cudaFuncSetAttribute(conv_kernel<1, 1, 8>,
                         cudaFuncAttributeMaxDynamicSharedMemorySize, SMEM_CONV);
    cudaFuncSetAttribute(conv_kernel<1, 0, 16>,
                         cudaFuncAttributeMaxDynamicSharedMemorySize, SMEM_CONV);
    cudaFuncSetAttribute(conv_kernel<1, 1, 16>,
                         cudaFuncAttributeMaxDynamicSharedMemorySize, SMEM_CONV);
    cudaFuncSetAttribute(conv_kernel<2, 0, 16>,
                         cudaFuncAttributeMaxDynamicSharedMemorySize, SMEM_CONV);

    // 0) weight prep (fragment layout + fp16 hi/lo split)
    prep_conv_w<<<672, 256>>>(tower_w);
    prep_proj_w<<<36, 256>>>(w_proj);

    // 1) projection -> split planes, buffer 0
    proj_kernel<<<dim3(1024, 2, 1), 256>>>(x);

    // 2) conv tower, ping-pong buffers; layer 6 writes fp32 into g_out
    dim3 gc(4, 2, NCH);
    const float* bl;
    bl = tower_b + 0 * HID; conv_kernel<1, 0, 4 ><<<gc, 256, SMEM_CONV>>>(bl, 2,   0);
    bl = tower_b + 1 * HID; conv_kernel<1, 1, 8 ><<<gc, 256, SMEM_CONV>>>(bl, 4,   1);
    bl = tower_b + 2 * HID; conv_kernel<1, 0, 16><<<gc, 256, SMEM_CONV>>>(bl, 8,   2);
    bl = tower_b + 3 * HID; conv_kernel<1, 1, 16><<<gc, 256, SMEM_CONV>>>(bl, 16,  3);
    bl = tower_b + 4 * HID; conv_kernel<1, 0, 16><<<gc, 256, SMEM_CONV>>>(bl, 32,  4);
    bl = tower_b + 5 * HID; conv_kernel<1, 1, 16><<<gc, 256, SMEM_CONV>>>(bl, 64,  5);
    bl = tower_b + 6 * HID; conv_kernel<2, 0, 16><<<gc, 256, SMEM_CONV>>>(bl, 128, 6);

    // 3) fused heads from g_out
    head_kernel<<<NCH, 512>>>(w_prof, b_prof, w_atpm, b_atpm, n_peaks, out);
}

// round 11
// speedup vs baseline: 1.2668x; 1.0349x over previous
#include <cuda_runtime.h>
#include <cuda_fp16.h>
#include <cstdint>

#define HID 256
#define LC 512
#define NCH 256
#define PLANE (HID*LC)
#define PR 768                         // padded row: 128 | 512 | 128 halves
#define CBUF ((size_t)NCH * HID * PR)  // halves per activation buffer plane
#define NR 131072                      // total rows (B*L)

// Split activation planes (hi fp16 / lo fp16), 2 ping-pong buffers each.
// Zero-initialized (BSS) -> pads stay zero forever; nothing ever writes them.
__device__ unsigned short gPH[2 * CBUF];
__device__ unsigned short gPL[2 * CBUF];
// Transposed, split input X: [m=288][r=131072] (rows 283..287 stay zero).
__device__ unsigned short gXTH[(size_t)288 * NR];
__device__ unsigned short gXTL[(size_t)288 * NR];
// Final-layer fp32 activations for the head.
__device__ float g_out[(size_t)NCH * PLANE];

// Fragment-layout weights: [layer][kt][mtile][lane] -> uint4 (8 halves, mma A-frag order)
__device__ uint4 WC_hi[7 * 48 * 16 * 32];
__device__ uint4 WC_lo[7 * 48 * 16 * 32];
__device__ uint4 WP_hi[18 * 16 * 32];
__device__ uint4 WP_lo[18 * 16 * 32];

// ---------------------------------------------------------------------------
__device__ __forceinline__ uint32_t smem_u32(const void* p) {
    uint32_t a;
    asm("{ .reg .u64 t; cvta.to.shared.u64 t, %1; cvt.u32.u64 %0, t; }" : "=r"(a) : "l"(p));
    return a;
}
__device__ __forceinline__ float gelu_res(float c) {
    return fmaf(0.5f * c, 1.0f + erff(c * 0.70710678118654752440f), c);
}
__device__ __forceinline__ uint32_t pack_hl(float v) {
    __half hh = __float2half_rn(v);
    float res = v - __half2float(hh);
    return (uint32_t)__half_as_ushort(hh) |
           ((uint32_t)__half_as_ushort(__float2half_rn(res)) << 16);
}
// two values -> packed hi-pair word and lo-pair word
__device__ __forceinline__ void pack2(float a, float b, uint32_t& hi, uint32_t& lo) {
    __half ah = __float2half_rn(a), bh = __float2half_rn(b);
    float ar = a - __half2float(ah), br = b - __half2float(bh);
    hi = (uint32_t)__half_as_ushort(ah) | ((uint32_t)__half_as_ushort(bh) << 16);
    lo = (uint32_t)__half_as_ushort(__float2half_rn(ar)) |
         ((uint32_t)__half_as_ushort(__float2half_rn(br)) << 16);
}
__device__ __forceinline__ void mma16816(float* d, const uint4 a, uint32_t b0, uint32_t b1) {
    asm volatile(
        "mma.sync.aligned.m16n8k16.row.col.f32.f16.f16.f32 "
        "{%0,%1,%2,%3}, {%4,%5,%6,%7}, {%8,%9}, {%0,%1,%2,%3};"
        : "+f"(d[0]), "+f"(d[1]), "+f"(d[2]), "+f"(d[3])
        : "r"(a.x), "r"(a.y), "r"(a.z), "r"(a.w), "r"(b0), "r"(b1));
}
__device__ __forceinline__ void ldmx4t(uint32_t& r0, uint32_t& r1, uint32_t& r2, uint32_t& r3,
                                       uint32_t addr) {
    asm volatile("ldmatrix.sync.aligned.m8n8.x4.trans.shared.b16 {%0,%1,%2,%3}, [%4];"
                 : "=r"(r0), "=r"(r1), "=r"(r2), "=r"(r3) : "r"(addr));
}
__device__ __forceinline__ uint4 lds128(uint32_t addr) {
    uint4 r;
    asm volatile("ld.shared.v4.u32 {%0,%1,%2,%3}, [%4];"
                 : "=r"(r.x), "=r"(r.y), "=r"(r.z), "=r"(r.w) : "r"(addr));
    return r;
}
__device__ __forceinline__ void cp16(uint32_t dst, const void* src) {
    asm volatile("cp.async.cg.shared.global [%0], [%1], 16;" :: "r"(dst), "l"(src));
}
__device__ __forceinline__ void cp8(uint32_t dst, const void* src) {
    asm volatile("cp.async.ca.shared.global [%0], [%1], 8;" :: "r"(dst), "l"(src));
}
__device__ __forceinline__ void cp4(uint32_t dst, const void* src) {
    asm volatile("cp.async.ca.shared.global [%0], [%1], 4;" :: "r"(dst), "l"(src));
}
#define CP_COMMIT() asm volatile("cp.async.commit_group;" ::: "memory")
#define CP_WAIT1()  asm volatile("cp.async.wait_group 1;" ::: "memory")

// ---------------------------------------------------------------------------
// Weight prep: fp32 -> (hi,lo) fp16 in mma A-fragment order.
// ---------------------------------------------------------------------------
__device__ __forceinline__ void split_pack(const float* v, uint4& hi, uint4& lo) {
    uint32_t hx[4], lx[4];
#pragma unroll
    for (int q = 0; q < 4; q++) {
        pack2(v[2 * q], v[2 * q + 1], hx[q], lx[q]);
    }
    hi = make_uint4(hx[0], hx[1], hx[2], hx[3]);
    lo = make_uint4(lx[0], lx[1], lx[2], lx[3]);
}

__global__ void prep_conv_w(const float* __restrict__ tw) {
    int idx = blockIdx.x * 256 + threadIdx.x;
    if (idx >= 7 * 48 * 16 * 32) return;
    int lane = idx & 31;
    int mt = (idx >> 5) & 15;
    int kt = (idx >> 9) % 48;
    int layer = (idx >> 9) / 48;
    int g = lane >> 2, t = lane & 3;
    const float* W = tw + (size_t)layer * 256 * 768;
    int r0 = mt * 16 + g, r1 = r0 + 8;
    int c0 = kt * 16 + 2 * t;
    float v[8];
    v[0] = W[r0 * 768 + c0];     v[1] = W[r0 * 768 + c0 + 1];
    v[2] = W[r1 * 768 + c0];     v[3] = W[r1 * 768 + c0 + 1];
    v[4] = W[r0 * 768 + c0 + 8]; v[5] = W[r0 * 768 + c0 + 9];
    v[6] = W[r1 * 768 + c0 + 8]; v[7] = W[r1 * 768 + c0 + 9];
    split_pack(v, WC_hi[idx], WC_lo[idx]);
}

__global__ void prep_proj_w(const float* __restrict__ wp) {
    int idx = blockIdx.x * 256 + threadIdx.x;
    if (idx >= 18 * 16 * 32) return;
    int lane = idx & 31;
    int mt = (idx >> 5) & 15;
    int kt = idx >> 9;
    int g = lane >> 2, t = lane & 3;
    int r0 = mt * 16 + g, r1 = r0 + 8;
    int c0 = kt * 16 + 2 * t;
    const int cs[4] = {c0, c0 + 1, c0 + 8, c0 + 9};
    float v[8];
    v[0] = (cs[0] < 283) ? wp[r0 * 283 + cs[0]] : 0.f;
    v[1] = (cs[1] < 283) ? wp[r0 * 283 + cs[1]] : 0.f;
    v[2] = (cs[0] < 283) ? wp[r1 * 283 + cs[0]] : 0.f;
    v[3] = (cs[1] < 283) ? wp[r1 * 283 + cs[1]] : 0.f;
    v[4] = (cs[2] < 283) ? wp[r0 * 283 + cs[2]] : 0.f;
    v[5] = (cs[3] < 283) ? wp[r0 * 283 + cs[3]] : 0.f;
    v[6] = (cs[2] < 283) ? wp[r1 * 283 + cs[2]] : 0.f;
    v[7] = (cs[3] < 283) ? wp[r1 * 283 + cs[3]] : 0.f;
    split_pack(v, WP_hi[idx], WP_lo[idx]);
}

// ---------------------------------------------------------------------------
// X convert+transpose: x[r][m] fp32 -> gXTH/gXTL[m][r] split fp16 planes.
// 32x32 tiles via smem; both global accesses coalesced.
// ---------------------------------------------------------------------------
__global__ __launch_bounds__(256) void convert_x(const float* __restrict__ x) {
    __shared__ float tile[32][33];
    const int rb = blockIdx.x * 32;
    const int mb = blockIdx.y * 32;
    const int tx = threadIdx.x & 31;
    const int ty = threadIdx.x >> 5;      // 0..7
#pragma unroll
    for (int k = 0; k < 4; k++) {
        int r = rb + ty + k * 8;
        int m = mb + tx;
        tile[ty + k * 8][tx] = (m < 283) ? x[(size_t)r * 283 + m] : 0.f;
    }
    __syncthreads();
#pragma unroll
    for (int k = 0; k < 4; k++) {
        int m = mb + ty + k * 8;
        int r = rb + tx;
        uint32_t p = pack_hl(tile[tx][ty + k * 8]);
        gXTH[(size_t)m * NR + r] = (unsigned short)(p & 0xffffu);
        gXTL[(size_t)m * NR + r] = (unsigned short)(p >> 16);
    }
}

// ---------------------------------------------------------------------------
// Unified GEMM kernel: all tile data via cp.async; 3-pair (6-slot) ring with
// wait_group 1. Commit happens AFTER the iteration barrier -> race-free.
// warp tile 64x32, CTA tile 128(M) x 128(N), 8 warps, 2 CTAs/SM.
// MODE 0: projection (B from gXT planes, no shift, KT=18, out split planes b0)
// MODE 1: conv, split planes out; MODE 2: conv, fp32 out (last layer).
// CSZ = worst-case B cp.async element size; tap=1 rows always use cp16.
// ---------------------------------------------------------------------------
#define SSTR 136
#define A_SLOT 8192
#define A_REG (6 * A_SLOT)           // 49152
#define B_PLANE 4352
#define SMEM_CONV (A_REG + 12 * B_PLANE)   // 101376

template <int MODE, int BUF, int CSZ>
__global__ __launch_bounds__(256, 2) void conv_kernel(
    const float* __restrict__ bias, int dil, int layer)
{
    extern __shared__ char dsm[];
    const uint32_t sm0 = smem_u32(dsm);
    const uint32_t sA = sm0;                 // A slots (6)
    const uint32_t sB = sm0 + A_REG;         // B planes (12)

    constexpr int KT = (MODE == 0) ? 18 : 48;

    const int tid = threadIdx.x;
    const int lane = tid & 31;
    const int wid = tid >> 5;
    const int wm = wid >> 2;      // 0..1
    const int wn = wid & 3;       // 0..3
    const int mbase = blockIdx.y * 128;
    const int mt8 = blockIdx.y * 8;
    const int n = blockIdx.z;
    const int l0 = blockIdx.x * 128;

    const uint4* __restrict__ WAhi =
        (MODE == 0) ? WP_hi : (WC_hi + (size_t)layer * 48 * 16 * 32);
    const uint4* __restrict__ WAlo =
        (MODE == 0) ? WP_lo : (WC_lo + (size_t)layer * 48 * 16 * 32);
    const unsigned short* __restrict__ inH = gPH + (size_t)BUF * CBUF;
    const unsigned short* __restrict__ inL = gPL + (size_t)BUF * CBUF;

    // A cp.async: 256 threads x (hi 16B + lo 16B) per kt
    const int amt = tid >> 5;
    auto cpA = [&](int kt, int q) {
        size_t src = (size_t)(kt * 16 + mt8 + amt) * 32 + lane;
        uint32_t d = sA + q * A_SLOT + tid * 16;
        cp16(d, WAhi + src);
        cp16(d + 4096, WAlo + src);
    };

    // B cp.async: thread -> (k-row kk, 8 consecutive l at ll0)
    const int kk = tid >> 4;
    const int ll0 = (tid & 15) * 8;
    auto cpB = [&](int kt, int q) {
        int kg = kt * 16 + kk;
        uint32_t dH = sB + (uint32_t)(q * 2 + 0) * B_PLANE + (uint32_t)((kk * SSTR + ll0) * 2);
        uint32_t dL = sB + (uint32_t)(q * 2 + 1) * B_PLANE + (uint32_t)((kk * SSTR + ll0) * 2);
        if (MODE == 0) {
            size_t off = (size_t)kg * NR + l0 + ll0;
            cp16(dH, gXTH + off);
            cp16(dL, gXTL + off);
        } else {
            int ci = kg / 3;
            int rem = kg - 3 * ci;
            int sh = (rem - 1) * dil;
            size_t off = ((size_t)n * HID + ci) * PR + 128 + l0 + ll0 + sh;
            const unsigned short* srcH = inH + off;
            const unsigned short* srcL = inL + off;
            if (CSZ == 16 || rem == 1) {
                cp16(dH, srcH);
                cp16(dL, srcL);
            } else if (CSZ == 8) {
                cp8(dH, srcH);     cp8(dH + 8, srcH + 4);
                cp8(dL, srcL);     cp8(dL + 8, srcL + 4);
            } else {
                cp4(dH, srcH);      cp4(dH + 4, srcH + 2);
                cp4(dH + 8, srcH + 4); cp4(dH + 12, srcH + 6);
                cp4(dL, srcL);      cp4(dL + 4, srcL + 2);
                cp4(dL + 8, srcL + 4); cp4(dL + 12, srcL + 6);
            }
        }
    };

    float acc[4][4][4];
#pragma unroll
    for (int i = 0; i < 4; i++)
#pragma unroll
        for (int j = 0; j < 4; j++)
#pragma unroll
            for (int q = 0; q < 4; q++) acc[i][j][q] = 0.f;

    // ldmatrix.trans lane addressing
    const int grp = lane >> 3, lwi = lane & 7;
    const int krow = (grp & 1) * 8 + lwi;
    const int ncol = wn * 32 + (grp >> 1) * 8;

    auto mma_block = [&](int q) {
        uint32_t ph = sB + (uint32_t)(q * 2 + 0) * B_PLANE;
        uint32_t pl = sB + (uint32_t)(q * 2 + 1) * B_PLANE;
        uint32_t bh[4][2], bl[4][2];
#pragma unroll
        for (int jj = 0; jj < 2; jj++) {
            uint32_t r0, r1, r2, r3;
            ldmx4t(r0, r1, r2, r3, ph + (uint32_t)((krow * SSTR + ncol + jj * 16) * 2));
            bh[jj * 2][0] = r0;     bh[jj * 2][1] = r1;
            bh[jj * 2 + 1][0] = r2; bh[jj * 2 + 1][1] = r3;
            ldmx4t(r0, r1, r2, r3, pl + (uint32_t)((krow * SSTR + ncol + jj * 16) * 2));
            bl[jj * 2][0] = r0;     bl[jj * 2][1] = r1;
            bl[jj * 2 + 1][0] = r2; bl[jj * 2 + 1][1] = r3;
        }
        uint32_t abase = sA + (uint32_t)q * A_SLOT;
#pragma unroll
        for (int ih = 0; ih < 4; ih += 2) {
            uint4 Ah[2], Al[2];
#pragma unroll
            for (int u = 0; u < 2; u++) {
                uint32_t ao = abase + (uint32_t)(((wm * 4 + ih + u) * 32 + lane) * 16);
                Ah[u] = lds128(ao);
                Al[u] = lds128(ao + 4096);
            }
#pragma unroll
            for (int u = 0; u < 2; u++)
#pragma unroll
                for (int j = 0; j < 4; j++) {
                    mma16816(acc[ih + u][j], Ah[u], bh[j][0], bh[j][1]);
                    mma16816(acc[ih + u][j], Ah[u], bl[j][0], bl[j][1]);
                    mma16816(acc[ih + u][j], Al[u], bh[j][0], bh[j][1]);
                }
        }
    };

    // prologue: pairs 0 (kt 0,1) and 1 (kt 2,3), one commit group each
    cpA(0, 0); cpB(0, 0);
    cpA(1, 1); cpB(1, 1);
    CP_COMMIT();
    cpA(2, 2); cpB(2, 2);
    cpA(3, 3); cpB(3, 3);
    CP_COMMIT();

    for (int kt2 = 0; kt2 < KT; kt2 += 2) {
        const int pr3 = (kt2 >> 1) % 3;          // current pair 0..2
        CP_WAIT1();                               // current pair's group retired
        __syncthreads();                          // all readers of pair (i-1) done
        if (kt2 + 4 < KT) {
            const int pn = pr3 == 0 ? 2 : pr3 - 1;   // (pr3+2)%3
            cpA(kt2 + 4, pn * 2);     cpB(kt2 + 4, pn * 2);
            cpA(kt2 + 5, pn * 2 + 1); cpB(kt2 + 5, pn * 2 + 1);
        }
        CP_COMMIT();                              // commit (possibly empty) group
        mma_block(pr3 * 2);
        mma_block(pr3 * 2 + 1);
    }

    // ---- epilogue ----
    const int g = lane >> 2, t4 = lane & 3;
    if (MODE == 0) {
        const int nn = l0 >> 9;
        const int lp0 = l0 & 511;
#pragma unroll
        for (int i = 0; i < 4; i++) {
            int co0 = mbase + wm * 64 + i * 16 + g;
#pragma unroll
            for (int j = 0; j < 4; j++) {
                int lp = lp0 + wn * 32 + j * 8 + 2 * t4;
                size_t r0i = ((size_t)nn * HID + co0) * PR + 128 + lp;
                size_t r1i = ((size_t)nn * HID + co0 + 8) * PR + 128 + lp;
                uint32_t h01, l01, h23, l23;
                pack2(acc[i][j][0], acc[i][j][1], h01, l01);
                pack2(acc[i][j][2], acc[i][j][3], h23, l23);
                *(uint32_t*)&gPH[r0i] = h01; *(uint32_t*)&gPL[r0i] = l01;
                *(uint32_t*)&gPH[r1i] = h23; *(uint32_t*)&gPL[r1i] = l23;
            }
        }
    } else if (MODE == 1) {
        unsigned short* oH = gPH + (size_t)(1 - BUF) * CBUF;
        unsigned short* oL = gPL + (size_t)(1 - BUF) * CBUF;
#pragma unroll
        for (int i = 0; i < 4; i++) {
            int co0 = mbase + wm * 64 + i * 16 + g;
            float b0 = bias[co0], b1 = bias[co0 + 8];
#pragma unroll
            for (int j = 0; j < 4; j++) {
                int lp = l0 + wn * 32 + j * 8 + 2 * t4;
                size_t r0i = ((size_t)n * HID + co0) * PR + 128 + lp;
                size_t r1i = ((size_t)n * HID + co0 + 8) * PR + 128 + lp;
                uint32_t h01, l01, h23, l23;
                pack2(gelu_res(acc[i][j][0] + b0), gelu_res(acc[i][j][1] + b0), h01, l01);
                pack2(gelu_res(acc[i][j][2] + b1), gelu_res(acc[i][j][3] + b1), h23, l23);
                *(uint32_t*)&oH[r0i] = h01; *(uint32_t*)&oL[r0i] = l01;
                *(uint32_t*)&oH[r1i] = h23; *(uint32_t*)&oL[r1i] = l23;
            }
        }
    } else {
#pragma unroll
        for (int i = 0; i < 4; i++) {
            int co0 = mbase + wm * 64 + i * 16 + g;
            float b0 = bias[co0], b1 = bias[co0 + 8];
#pragma unroll
            for (int j = 0; j < 4; j++) {
                int lp = l0 + wn * 32 + j * 8 + 2 * t4;
                float2 v0, v1;
                v0.x = gelu_res(acc[i][j][0] + b0);
                v0.y = gelu_res(acc[i][j][1] + b0);
                v1.x = gelu_res(acc[i][j][2] + b1);
                v1.y = gelu_res(acc[i][j][3] + b1);
                *(float2*)&g_out[(size_t)n * PLANE + (size_t)co0 * 512 + lp] = v0;
                *(float2*)&g_out[(size_t)n * PLANE + (size_t)(co0 + 8) * 512 + lp] = v1;
            }
        }
    }
}

// ---------------------------------------------------------------------------
// Head: profile conv (K=20, pad (9,10)) + mean pool + atpm, fused.
// ---------------------------------------------------------------------------
__global__ __launch_bounds__(512) void head_kernel(const float* __restrict__ wprof,
                                                   const float* __restrict__ bprof,
                                                   const float* __restrict__ watpm,
                                                   const float* __restrict__ batpm,
                                                   const int* __restrict__ np_raw,
                                                   float* __restrict__ out) {
    __shared__ float buf[2][544];
    __shared__ float wp[HID * 20];
    __shared__ float wa[HID];
    __shared__ float red[16];

    const int n = blockIdx.x;
    const int tid = threadIdx.x;
    const float* h = g_out + (size_t)n * PLANE;

    for (int i = tid; i < HID * 20; i += 512) wp[i] = wprof[i];
    if (tid < HID) wa[tid] = watpm[tid];
    if (tid < 9)  { buf[0][tid] = 0.f; buf[1][tid] = 0.f; }
    if (tid < 13) { buf[0][521 + tid] = 0.f; buf[1][521 + tid] = 0.f; }

    float accp = 0.f, acca = 0.f;
    buf[0][9 + tid] = h[tid];
    __syncthreads();

    for (int c = 0; c < HID; c++) {
        const int cur = c & 1;
        if (c + 1 < HID) buf[cur ^ 1][9 + tid] = h[(c + 1) * LC + tid];
        acca = fmaf(buf[cur][9 + tid], wa[c], acca);
        const float* wr = &wp[c * 20];
#pragma unroll
        for (int k = 0; k < 20; k++)
            accp = fmaf(buf[cur][tid + k], wr[k], accp);
        __syncthreads();
    }

    out[256 + n * LC + tid] = accp + bprof[0];

#pragma unroll
    for (int o = 16; o > 0; o >>= 1) acca += __shfl_xor_sync(0xffffffffu, acca, o);
    if ((tid & 31) == 0) red[tid >> 5] = acca;
    __syncthreads();
    if (tid < 16) {
        float vv = red[tid];
#pragma unroll
        for (int o = 8; o > 0; o >>= 1) vv += __shfl_xor_sync(0x0000ffffu, vv, o);
        if (tid == 0) {
            int n0 = np_raw[0];
            int n1;
            int w1 = np_raw[1];
            if (w1 != 0) {
                n1 = w1;
            } else {
                int w2 = np_raw[2], w3 = np_raw[3];
                n1 = (w2 >= 0 && w2 < 128 && w3 == 0) ? w2 : 0;
            }
            float atpm = vv * (1.0f / 512.0f) + batpm[0];
            int p = n & 127, b = n >> 7;
            int lim = (b == 0) ? n0 : n1;
            out[n] = (p < lim) ? atpm : 0.f;
        }
    }
}

// ---------------------------------------------------------------------------
extern "C" void kernel_launch(void* const* d_in, const int* in_sizes, int n_in,
                              void* d_out, int out_size) {
    const float* x       = (const float*)d_in[0];
    const float* w_proj  = (const float*)d_in[1];
    const float* tower_w = (const float*)d_in[2];
    const float* tower_b = (const float*)d_in[3];
    const float* w_prof  = (const float*)d_in[4];
    const float* b_prof  = (const float*)d_in[5];
    const float* w_atpm  = (const float*)d_in[6];
    const float* b_atpm  = (const float*)d_in[7];
    const int*   n_peaks = (const int*)d_in[8];
    float* out = (float*)d_out;

    (void)in_sizes; (void)n_in; (void)out_size;

    cudaFuncSetAttribute(conv_kernel<0, 0, 16>,
                         cudaFuncAttributeMaxDynamicSharedMemorySize, SMEM_CONV);
    cudaFuncSetAttribute(conv_kernel<1, 0, 4>,
                         cudaFuncAttributeMaxDynamicSharedMemorySize, SMEM_CONV);
    cudaFuncSetAttribute(conv_kernel<1, 1, 8>,
                         cudaFuncAttributeMaxDynamicSharedMemorySize, SMEM_CONV);
    cudaFuncSetAttribute(conv_kernel<1, 0, 16>,
                         cudaFuncAttributeMaxDynamicSharedMemorySize, SMEM_CONV);
    cudaFuncSetAttribute(conv_kernel<1, 1, 16>,
                         cudaFuncAttributeMaxDynamicSharedMemorySize, SMEM_CONV);
    cudaFuncSetAttribute(conv_kernel<2, 0, 16>,
                         cudaFuncAttributeMaxDynamicSharedMemorySize, SMEM_CONV);

    // 0) weight prep + X convert/transpose
    prep_conv_w<<<672, 256>>>(tower_w);
    prep_proj_w<<<36, 256>>>(w_proj);
    convert_x<<<dim3(NR / 32, 9), 256>>>(x);

    // 1) projection -> split planes, buffer 0 (deep-pipelined GEMM)
    conv_kernel<0, 0, 16><<<dim3(1024, 2, 1), 256, SMEM_CONV>>>(nullptr, 0, 0);

    // 2) conv tower, ping-pong buffers; layer 6 writes fp32 into g_out
    dim3 gc(4, 2, NCH);
    const float* bl;
    bl = tower_b + 0 * HID; conv_kernel<1, 0, 4 ><<<gc, 256, SMEM_CONV>>>(bl, 2,   0);
    bl = tower_b + 1 * HID; conv_kernel<1, 1, 8 ><<<gc, 256, SMEM_CONV>>>(bl, 4,   1);
    bl = tower_b + 2 * HID; conv_kernel<1, 0, 16><<<gc, 256, SMEM_CONV>>>(bl, 8,   2);
    bl = tower_b + 3 * HID; conv_kernel<1, 1, 16><<<gc, 256, SMEM_CONV>>>(bl, 16,  3);
    bl = tower_b + 4 * HID; conv_kernel<1, 0, 16><<<gc, 256, SMEM_CONV>>>(bl, 32,  4);
    bl = tower_b + 5 * HID; conv_kernel<1, 1, 16><<<gc, 256, SMEM_CONV>>>(bl, 64,  5);
    bl = tower_b + 6 * HID; conv_kernel<2, 0, 16><<<gc, 256, SMEM_CONV>>>(bl, 128, 6);

    // 3) fused heads from g_out
    head_kernel<<<NCH, 512>>>(w_prof, b_prof, w_atpm, b_atpm, n_peaks, out);
}